// round 2
// baseline (speedup 1.0000x reference)
#include <cuda_runtime.h>
#include <math.h>

#define IN_F  2048
#define OUT_F 2048
#define NROWS 8192   // 4 * 2048

// ---- scratch (no allocation allowed; __device__ globals) ----
__device__ float g_keys[(size_t)OUT_F * IN_F];   // 16 MB
__device__ float g_knorm[OUT_F];
__device__ float g_xnorm[NROWS];

// softplus, numerically stable: max(x,0) + log1p(exp(-|x|))
__device__ __forceinline__ float softplus_f(float x) {
    return fmaxf(x, 0.0f) + log1pf(expf(-fabsf(x)));
}

// ---------------------------------------------------------------------------
// Kernel 1: keys = mu_w * softplus(sigma_w); k_norm = ||keys_row||  (1 block/row)
// ---------------------------------------------------------------------------
__global__ void prep_keys_kernel(const float* __restrict__ muw,
                                 const float* __restrict__ sgw) {
    const int row = blockIdx.x;
    const size_t base = (size_t)row * IN_F;
    float ss = 0.0f;
    for (int i = threadIdx.x * 4; i < IN_F; i += blockDim.x * 4) {
        float4 m = *(const float4*)(muw + base + i);
        float4 s = *(const float4*)(sgw + base + i);
        float4 k;
        k.x = m.x * softplus_f(s.x);
        k.y = m.y * softplus_f(s.y);
        k.z = m.z * softplus_f(s.z);
        k.w = m.w * softplus_f(s.w);
        *(float4*)(g_keys + base + i) = k;
        ss += k.x*k.x + k.y*k.y + k.z*k.z + k.w*k.w;
    }
    __shared__ float red[256];
    red[threadIdx.x] = ss;
    __syncthreads();
    for (int s = 128; s > 0; s >>= 1) {
        if (threadIdx.x < s) red[threadIdx.x] += red[threadIdx.x + s];
        __syncthreads();
    }
    if (threadIdx.x == 0) g_knorm[row] = sqrtf(red[0]);
}

// ---------------------------------------------------------------------------
// Kernel 2: x_norm per row of x  (1 block/row)
// ---------------------------------------------------------------------------
__global__ void prep_xnorm_kernel(const float* __restrict__ x) {
    const int row = blockIdx.x;
    const size_t base = (size_t)row * IN_F;
    float ss = 0.0f;
    for (int i = threadIdx.x * 4; i < IN_F; i += blockDim.x * 4) {
        float4 v = *(const float4*)(x + base + i);
        ss += v.x*v.x + v.y*v.y + v.z*v.z + v.w*v.w;
    }
    __shared__ float red[256];
    red[threadIdx.x] = ss;
    __syncthreads();
    for (int s = 128; s > 0; s >>= 1) {
        if (threadIdx.x < s) red[threadIdx.x] += red[threadIdx.x + s];
        __syncthreads();
    }
    if (threadIdx.x == 0) g_xnorm[row] = sqrtf(red[0]);
}

// ---------------------------------------------------------------------------
// Kernel 3: fused dual GEMM + epilogue.
//   C1[n,o] = sum_k x[n,k] * keys[o,k]    (dots)
//   C2[n,o] = sum_k x[n,k] * mu_w[o,k]    (comp, pre-bias)
//   scores  = C1 / max(x_norm[n]*k_norm[o], 1e-8)
//   masked  = (C2 + bias[o]) * relu(scores - gate[o])
//   out[0..NO)      = masked (== output)
//   out[NO..2NO)    = scores
//   out[2NO..3NO)   = masked
// Tiling: BM=128, BN=64, BK=16, 256 threads, per-thread 8x4 per matrix.
// ---------------------------------------------------------------------------
#define BM 128
#define BN 64
#define BK 16
#define TM 8
#define TN 4
#define AP 4   // padding on As leading dim

__global__ __launch_bounds__(256)
void moie_gemm_kernel(const float* __restrict__ x,
                      const float* __restrict__ muw,
                      const float* __restrict__ gate,
                      const float* __restrict__ bias,
                      float* __restrict__ out) {
    __shared__ float As[BK][BM + AP];   // x tile, [k][m]
    __shared__ float Bk[BK][BN];        // keys tile, [k][n]
    __shared__ float Bm[BK][BN];        // mu_w tile, [k][n]

    const int tid = threadIdx.x;
    const int tx = tid & 15;   // n-dir, 16 threads * 4 = 64
    const int ty = tid >> 4;   // m-dir, 16 threads * 8 = 128
    const int mBase = blockIdx.y * BM;
    const int nBase = blockIdx.x * BN;

    float acc1[TM][TN];
    float acc2[TM][TN];
    #pragma unroll
    for (int i = 0; i < TM; i++)
        #pragma unroll
        for (int j = 0; j < TN; j++) { acc1[i][j] = 0.0f; acc2[i][j] = 0.0f; }

    // A-tile load map: 128 rows x 16 cols = 512 float4; 2 per thread
    const int aRow0 = tid >> 1;              // (tid*2)/4
    const int aCv0  = (tid * 2) & 3;
    const int aCv1  = (tid * 2 + 1) & 3;
    // B-tile load map: 64 rows x 16 cols = 256 float4; 1 per thread
    const int bRow = tid >> 2;
    const int bCv  = tid & 3;

    for (int k0 = 0; k0 < IN_F; k0 += BK) {
        // ---- load A tile (transposed into As[k][m]) ----
        {
            const float* ap = x + (size_t)(mBase + aRow0) * IN_F + k0;
            float4 v0 = *(const float4*)(ap + aCv0 * 4);
            As[aCv0*4 + 0][aRow0] = v0.x;
            As[aCv0*4 + 1][aRow0] = v0.y;
            As[aCv0*4 + 2][aRow0] = v0.z;
            As[aCv0*4 + 3][aRow0] = v0.w;
            float4 v1 = *(const float4*)(ap + aCv1 * 4);
            As[aCv1*4 + 0][aRow0] = v1.x;
            As[aCv1*4 + 1][aRow0] = v1.y;
            As[aCv1*4 + 2][aRow0] = v1.z;
            As[aCv1*4 + 3][aRow0] = v1.w;
        }
        // ---- load both B tiles ----
        {
            size_t off = (size_t)(nBase + bRow) * IN_F + k0 + bCv * 4;
            float4 vk = *(const float4*)(g_keys + off);
            Bk[bCv*4 + 0][bRow] = vk.x;
            Bk[bCv*4 + 1][bRow] = vk.y;
            Bk[bCv*4 + 2][bRow] = vk.z;
            Bk[bCv*4 + 3][bRow] = vk.w;
            float4 vm = *(const float4*)(muw + off);
            Bm[bCv*4 + 0][bRow] = vm.x;
            Bm[bCv*4 + 1][bRow] = vm.y;
            Bm[bCv*4 + 2][bRow] = vm.z;
            Bm[bCv*4 + 3][bRow] = vm.w;
        }
        __syncthreads();

        #pragma unroll
        for (int k = 0; k < BK; k++) {
            float a[TM], b1[TN], b2[TN];
            float4 a0 = *(const float4*)&As[k][ty * TM];
            float4 a1 = *(const float4*)&As[k][ty * TM + 4];
            a[0]=a0.x; a[1]=a0.y; a[2]=a0.z; a[3]=a0.w;
            a[4]=a1.x; a[5]=a1.y; a[6]=a1.z; a[7]=a1.w;
            float4 bb1 = *(const float4*)&Bk[k][tx * TN];
            b1[0]=bb1.x; b1[1]=bb1.y; b1[2]=bb1.z; b1[3]=bb1.w;
            float4 bb2 = *(const float4*)&Bm[k][tx * TN];
            b2[0]=bb2.x; b2[1]=bb2.y; b2[2]=bb2.z; b2[3]=bb2.w;
            #pragma unroll
            for (int i = 0; i < TM; i++)
                #pragma unroll
                for (int j = 0; j < TN; j++) {
                    acc1[i][j] = fmaf(a[i], b1[j], acc1[i][j]);
                    acc2[i][j] = fmaf(a[i], b2[j], acc2[i][j]);
                }
        }
        __syncthreads();
    }

    // ---- epilogue ----
    float xn[TM], kn[TN], gt[TN], bs[TN];
    #pragma unroll
    for (int i = 0; i < TM; i++) xn[i] = g_xnorm[mBase + ty * TM + i];
    #pragma unroll
    for (int j = 0; j < TN; j++) {
        int c = nBase + tx * TN + j;
        kn[j] = g_knorm[c];
        gt[j] = gate[c];
        bs[j] = bias[c];
    }
    const size_t NO = (size_t)NROWS * OUT_F;
    #pragma unroll
    for (int i = 0; i < TM; i++) {
        const int m = mBase + ty * TM + i;
        const int c = nBase + tx * TN;
        float4 sc4, mk4;
        float sc[TN], mk[TN];
        #pragma unroll
        for (int j = 0; j < TN; j++) {
            float denom = fmaxf(xn[i] * kn[j], 1e-8f);
            float score = acc1[i][j] / denom;
            float w = fmaxf(score - gt[j], 0.0f);
            float masked = (acc2[i][j] + bs[j]) * w;
            sc[j] = score; mk[j] = masked;
        }
        sc4.x=sc[0]; sc4.y=sc[1]; sc4.z=sc[2]; sc4.w=sc[3];
        mk4.x=mk[0]; mk4.y=mk[1]; mk4.z=mk[2]; mk4.w=mk[3];
        size_t idx = (size_t)m * OUT_F + c;
        *(float4*)(out + idx)          = mk4;   // output
        *(float4*)(out + NO + idx)     = sc4;   // scores
        *(float4*)(out + 2 * NO + idx) = mk4;   // masked
    }
}

// ---------------------------------------------------------------------------
extern "C" void kernel_launch(void* const* d_in, const int* in_sizes, int n_in,
                              void* d_out, int out_size) {
    const float* x    = (const float*)d_in[0];
    const float* muw  = (const float*)d_in[1];
    const float* sgw  = (const float*)d_in[2];
    const float* gate = (const float*)d_in[3];
    const float* bias = (const float*)d_in[4];
    float* out = (float*)d_out;

    prep_keys_kernel<<<OUT_F, 256>>>(muw, sgw);
    prep_xnorm_kernel<<<NROWS, 256>>>(x);
    dim3 grid(OUT_F / BN, NROWS / BM);
    moie_gemm_kernel<<<grid, 256>>>(x, muw, gate, bias, out);
}

// round 4
// speedup vs baseline: 3.4549x; 3.4549x over previous
#include <cuda_runtime.h>
#include <cuda_bf16.h>
#include <mma.h>
#include <math.h>
#include <stdint.h>

using namespace nvcuda;

#define IN_F  2048
#define OUT_F 2048
#define NROWS 8192   // 4 * 2048

// ---------------------------------------------------------------------------
// Scratch (__device__ globals; no runtime allocation allowed)
// ---------------------------------------------------------------------------
__device__ __align__(16) __nv_bfloat16 g_xh[(size_t)NROWS * IN_F];
__device__ __align__(16) __nv_bfloat16 g_xl[(size_t)NROWS * IN_F];
__device__ __align__(16) __nv_bfloat16 g_kh[(size_t)OUT_F * IN_F];
__device__ __align__(16) __nv_bfloat16 g_kl[(size_t)OUT_F * IN_F];
__device__ __align__(16) __nv_bfloat16 g_mh[(size_t)OUT_F * IN_F];
__device__ __align__(16) __nv_bfloat16 g_ml[(size_t)OUT_F * IN_F];
__device__ float g_knorm[OUT_F];
__device__ float g_xnorm[NROWS];

__device__ __forceinline__ float softplus_f(float x) {
    return fmaxf(x, 0.0f) + log1pf(expf(-fabsf(x)));
}

__device__ __forceinline__ void cp16(uint32_t sa, const void* gp) {
    asm volatile("cp.async.cg.shared.global [%0], [%1], 16;"
                 :: "r"(sa), "l"(__cvta_generic_to_global(gp)) : "memory");
}
#define CP_COMMIT() asm volatile("cp.async.commit_group;" ::: "memory")
#define CP_WAIT(n)  asm volatile("cp.async.wait_group %0;" :: "n"(n) : "memory")

__device__ __forceinline__ uint32_t smem_u32(const void* p) {
    uint32_t a;
    asm("{ .reg .u64 t; cvta.to.shared.u64 t, %1; cvt.u32.u64 %0, t; }" : "=r"(a) : "l"(p));
    return a;
}

// ---------------------------------------------------------------------------
// Prep 1: keys = muw*softplus(sgw); knorm; split keys & muw into bf16 hi/lo.
// grid = OUT_F, 256 threads, 8 elements/thread.
// ---------------------------------------------------------------------------
__global__ __launch_bounds__(256) void prep_w(const float* __restrict__ muw,
                                              const float* __restrict__ sgw) {
    const int row = blockIdx.x;
    const int t = threadIdx.x;
    const size_t base = (size_t)row * IN_F + t * 8;
    float k[8], m[8];
    float4 m0 = *(const float4*)(muw + base);
    float4 m1 = *(const float4*)(muw + base + 4);
    float4 s0 = *(const float4*)(sgw + base);
    float4 s1 = *(const float4*)(sgw + base + 4);
    m[0]=m0.x; m[1]=m0.y; m[2]=m0.z; m[3]=m0.w; m[4]=m1.x; m[5]=m1.y; m[6]=m1.z; m[7]=m1.w;
    float s[8] = {s0.x,s0.y,s0.z,s0.w,s1.x,s1.y,s1.z,s1.w};
    float ss = 0.0f;
    #pragma unroll
    for (int j = 0; j < 8; j++) { k[j] = m[j] * softplus_f(s[j]); ss += k[j]*k[j]; }
    #pragma unroll
    for (int j = 0; j < 8; j += 2) {
        __nv_bfloat16 kh0 = __float2bfloat16(k[j]),   kh1 = __float2bfloat16(k[j+1]);
        __nv_bfloat16 kl0 = __float2bfloat16(k[j]   - __bfloat162float(kh0));
        __nv_bfloat16 kl1 = __float2bfloat16(k[j+1] - __bfloat162float(kh1));
        __nv_bfloat16 mh0 = __float2bfloat16(m[j]),   mh1 = __float2bfloat16(m[j+1]);
        __nv_bfloat16 ml0 = __float2bfloat16(m[j]   - __bfloat162float(mh0));
        __nv_bfloat16 ml1 = __float2bfloat16(m[j+1] - __bfloat162float(mh1));
        *(__nv_bfloat162*)(g_kh + base + j) = __nv_bfloat162(kh0, kh1);
        *(__nv_bfloat162*)(g_kl + base + j) = __nv_bfloat162(kl0, kl1);
        *(__nv_bfloat162*)(g_mh + base + j) = __nv_bfloat162(mh0, mh1);
        *(__nv_bfloat162*)(g_ml + base + j) = __nv_bfloat162(ml0, ml1);
    }
    __shared__ float red[256];
    red[t] = ss;
    __syncthreads();
    for (int st = 128; st > 0; st >>= 1) {
        if (t < st) red[t] += red[t + st];
        __syncthreads();
    }
    if (t == 0) g_knorm[row] = sqrtf(red[0]);
}

// ---------------------------------------------------------------------------
// Prep 2: xnorm; split x into bf16 hi/lo. grid = NROWS.
// ---------------------------------------------------------------------------
__global__ __launch_bounds__(256) void prep_x(const float* __restrict__ x) {
    const int row = blockIdx.x;
    const int t = threadIdx.x;
    const size_t base = (size_t)row * IN_F + t * 8;
    float4 v0 = *(const float4*)(x + base);
    float4 v1 = *(const float4*)(x + base + 4);
    float v[8] = {v0.x,v0.y,v0.z,v0.w,v1.x,v1.y,v1.z,v1.w};
    float ss = 0.0f;
    #pragma unroll
    for (int j = 0; j < 8; j++) ss += v[j]*v[j];
    #pragma unroll
    for (int j = 0; j < 8; j += 2) {
        __nv_bfloat16 h0 = __float2bfloat16(v[j]),   h1 = __float2bfloat16(v[j+1]);
        __nv_bfloat16 l0 = __float2bfloat16(v[j]   - __bfloat162float(h0));
        __nv_bfloat16 l1 = __float2bfloat16(v[j+1] - __bfloat162float(h1));
        *(__nv_bfloat162*)(g_xh + base + j) = __nv_bfloat162(h0, h1);
        *(__nv_bfloat162*)(g_xl + base + j) = __nv_bfloat162(l0, l1);
    }
    __shared__ float red[256];
    red[t] = ss;
    __syncthreads();
    for (int st = 128; st > 0; st >>= 1) {
        if (t < st) red[t] += red[t + st];
        __syncthreads();
    }
    if (t == 0) g_xnorm[row] = sqrtf(red[0]);
}

// ---------------------------------------------------------------------------
// Main WMMA kernel: CTA 128x128, 8 warps (4 in M, 2 in N), warp tile 32x64.
// Dual GEMM via bf16x3: dots = xh*kh + xh*kl + xl*kh; comp analogous with m.
// BK=32, double-buffered cp.async SMEM.
// ---------------------------------------------------------------------------
#define BK      32
#define LDT     40                        // padded row length (bf16 elems)
#define TILE_B  (128 * LDT * 2)           // 10240 bytes per operand tile
#define STAGE_B (6 * TILE_B)              // 61440
#define NIT     (IN_F / BK)               // 64
#define SMEM_SZ 131072                    // max(2*STAGE_B, 2*128*128*4)

__global__ __launch_bounds__(256, 1)
void moie_wmma_kernel(const float* __restrict__ gate,
                      const float* __restrict__ bias,
                      float* __restrict__ out) {
    extern __shared__ char smem[];
    const uint32_t sbase = smem_u32(smem);
    const int tid  = threadIdx.x;
    const int warp = tid >> 5;
    const int wm   = warp >> 1;          // 0..3  (M dir, 32 rows each)
    const int wn   = warp & 1;           // 0..1  (N dir, 64 cols each)
    const int mBase = blockIdx.y * 128;
    const int nBase = blockIdx.x * 128;

    // tile offsets within a stage (bytes)
    // 0:xh 1:xl 2:kh 3:kl 4:mh 5:ml
    const __nv_bfloat16* gsrc[6] = { g_xh, g_xl, g_kh, g_kl, g_mh, g_ml };
    const int            grow[6] = { mBase, mBase, nBase, nBase, nBase, nBase };

    wmma::fragment<wmma::accumulator, 16, 16, 16, float> accD[2][4];
    wmma::fragment<wmma::accumulator, 16, 16, 16, float> accC[2][4];
    #pragma unroll
    for (int i = 0; i < 2; i++)
        #pragma unroll
        for (int j = 0; j < 4; j++) {
            wmma::fill_fragment(accD[i][j], 0.0f);
            wmma::fill_fragment(accC[i][j], 0.0f);
        }

    // ---- async stage loader: 6 tiles x 512 vec16 / 256 threads = 12 per thr
    auto load_stage = [&](int stage_slot, int it) {
        const uint32_t sb = sbase + (uint32_t)stage_slot * STAGE_B;
        const int k0 = it * BK;
        #pragma unroll
        for (int tl = 0; tl < 6; ++tl) {
            const uint32_t tb = sb + tl * TILE_B;
            const __nv_bfloat16* gp = gsrc[tl];
            const int rb = grow[tl];
            #pragma unroll
            for (int t = 0; t < 2; ++t) {
                const int v   = tid + t * 256;      // 0..511
                const int row = v >> 2;             // 0..127
                const int c16 = v & 3;              // 0..3  (16B chunks of 64B row)
                cp16(tb + row * (LDT * 2) + c16 * 16,
                     gp + (size_t)(rb + row) * IN_F + k0 + c16 * 8);
            }
        }
    };

    load_stage(0, 0);
    CP_COMMIT();

    for (int it = 0; it < NIT; ++it) {
        const int cur = it & 1;
        if (it + 1 < NIT) {
            load_stage(cur ^ 1, it + 1);
            CP_COMMIT();
            CP_WAIT(1);
        } else {
            CP_WAIT(0);
        }
        __syncthreads();

        const __nv_bfloat16* st = (const __nv_bfloat16*)(smem + (size_t)cur * STAGE_B);
        const __nv_bfloat16* Axh = st;
        const __nv_bfloat16* Axl = st + 128 * LDT;
        const __nv_bfloat16* Bkh = st + 2 * 128 * LDT;
        const __nv_bfloat16* Bkl = st + 3 * 128 * LDT;
        const __nv_bfloat16* Bmh = st + 4 * 128 * LDT;
        const __nv_bfloat16* Bml = st + 5 * 128 * LDT;

        #pragma unroll
        for (int ks = 0; ks < BK / 16; ++ks) {
            wmma::fragment<wmma::matrix_a, 16, 16, 16, __nv_bfloat16, wmma::row_major> ah[2], al[2];
            #pragma unroll
            for (int mi = 0; mi < 2; ++mi) {
                wmma::load_matrix_sync(ah[mi], Axh + (wm * 32 + mi * 16) * LDT + ks * 16, LDT);
                wmma::load_matrix_sync(al[mi], Axl + (wm * 32 + mi * 16) * LDT + ks * 16, LDT);
            }
            wmma::fragment<wmma::matrix_b, 16, 16, 16, __nv_bfloat16, wmma::col_major> b[4];
            // kh: dots += xh*kh + xl*kh
            #pragma unroll
            for (int ni = 0; ni < 4; ++ni)
                wmma::load_matrix_sync(b[ni], Bkh + (wn * 64 + ni * 16) * LDT + ks * 16, LDT);
            #pragma unroll
            for (int mi = 0; mi < 2; ++mi)
                #pragma unroll
                for (int ni = 0; ni < 4; ++ni) {
                    wmma::mma_sync(accD[mi][ni], ah[mi], b[ni], accD[mi][ni]);
                    wmma::mma_sync(accD[mi][ni], al[mi], b[ni], accD[mi][ni]);
                }
            // kl: dots += xh*kl
            #pragma unroll
            for (int ni = 0; ni < 4; ++ni)
                wmma::load_matrix_sync(b[ni], Bkl + (wn * 64 + ni * 16) * LDT + ks * 16, LDT);
            #pragma unroll
            for (int mi = 0; mi < 2; ++mi)
                #pragma unroll
                for (int ni = 0; ni < 4; ++ni)
                    wmma::mma_sync(accD[mi][ni], ah[mi], b[ni], accD[mi][ni]);
            // mh: comp += xh*mh + xl*mh
            #pragma unroll
            for (int ni = 0; ni < 4; ++ni)
                wmma::load_matrix_sync(b[ni], Bmh + (wn * 64 + ni * 16) * LDT + ks * 16, LDT);
            #pragma unroll
            for (int mi = 0; mi < 2; ++mi)
                #pragma unroll
                for (int ni = 0; ni < 4; ++ni) {
                    wmma::mma_sync(accC[mi][ni], ah[mi], b[ni], accC[mi][ni]);
                    wmma::mma_sync(accC[mi][ni], al[mi], b[ni], accC[mi][ni]);
                }
            // ml: comp += xh*ml
            #pragma unroll
            for (int ni = 0; ni < 4; ++ni)
                wmma::load_matrix_sync(b[ni], Bml + (wn * 64 + ni * 16) * LDT + ks * 16, LDT);
            #pragma unroll
            for (int mi = 0; mi < 2; ++mi)
                #pragma unroll
                for (int ni = 0; ni < 4; ++ni)
                    wmma::mma_sync(accC[mi][ni], ah[mi], b[ni], accC[mi][ni]);
        }
        __syncthreads();
    }

    // ---- epilogue: dump accumulators to SMEM, then fused scalar math ----
    float* sD = (float*)smem;            // dots  128x128
    float* sC = sD + 128 * 128;          // comp  128x128
    #pragma unroll
    for (int mi = 0; mi < 2; ++mi)
        #pragma unroll
        for (int ni = 0; ni < 4; ++ni) {
            const int r = wm * 32 + mi * 16;
            const int c = wn * 64 + ni * 16;
            wmma::store_matrix_sync(sD + r * 128 + c, accD[mi][ni], 128, wmma::mem_row_major);
            wmma::store_matrix_sync(sC + r * 128 + c, accC[mi][ni], 128, wmma::mem_row_major);
        }
    __syncthreads();

    const size_t NO = (size_t)NROWS * OUT_F;
    #pragma unroll
    for (int e = 0; e < 16; ++e) {
        const int lin = e * 256 + tid;       // float4 index, 0..4095
        const int row = lin >> 5;            // 0..127
        const int c4  = (lin & 31) * 4;      // 0..124
        const int m   = mBase + row;
        const float xn = g_xnorm[m];
        float4 d = *(float4*)(sD + row * 128 + c4);
        float4 c = *(float4*)(sC + row * 128 + c4);
        float sc[4], mk[4];
        const float* dv = &d.x;
        const float* cv = &c.x;
        #pragma unroll
        for (int j = 0; j < 4; ++j) {
            const int n = nBase + c4 + j;
            const float score = dv[j] / fmaxf(xn * g_knorm[n], 1e-8f);
            const float w = fmaxf(score - gate[n], 0.0f);
            sc[j] = score;
            mk[j] = (cv[j] + bias[n]) * w;
        }
        float4 sc4 = make_float4(sc[0], sc[1], sc[2], sc[3]);
        float4 mk4 = make_float4(mk[0], mk[1], mk[2], mk[3]);
        const size_t idx = (size_t)m * OUT_F + nBase + c4;
        *(float4*)(out + idx)          = mk4;   // output
        *(float4*)(out + NO + idx)     = sc4;   // scores
        *(float4*)(out + 2 * NO + idx) = mk4;   // masked
    }
}

// ---------------------------------------------------------------------------
extern "C" void kernel_launch(void* const* d_in, const int* in_sizes, int n_in,
                              void* d_out, int out_size) {
    const float* x    = (const float*)d_in[0];
    const float* muw  = (const float*)d_in[1];
    const float* sgw  = (const float*)d_in[2];
    const float* gate = (const float*)d_in[3];
    const float* bias = (const float*)d_in[4];
    float* out = (float*)d_out;

    cudaFuncSetAttribute(moie_wmma_kernel, cudaFuncAttributeMaxDynamicSharedMemorySize, SMEM_SZ);

    prep_w<<<OUT_F, 256>>>(muw, sgw);
    prep_x<<<NROWS, 256>>>(x);
    dim3 grid(OUT_F / 128, NROWS / 128);
    moie_wmma_kernel<<<grid, 256, SMEM_SZ>>>(gate, bias, out);
}

// round 5
// speedup vs baseline: 3.9061x; 1.1306x over previous
#include <cuda_runtime.h>
#include <cuda_bf16.h>
#include <math.h>
#include <stdint.h>

#define IN_F  2048
#define OUT_F 2048
#define NROWS 8192   // 4 * 2048

// ---------------------------------------------------------------------------
// Scratch (__device__ globals; no runtime allocation allowed)
// ---------------------------------------------------------------------------
__device__ __align__(16) __nv_bfloat16 g_xh[(size_t)NROWS * IN_F];
__device__ __align__(16) __nv_bfloat16 g_xl[(size_t)NROWS * IN_F];
__device__ __align__(16) __nv_bfloat16 g_kh[(size_t)OUT_F * IN_F];
__device__ __align__(16) __nv_bfloat16 g_kl[(size_t)OUT_F * IN_F];
__device__ __align__(16) __nv_bfloat16 g_mh[(size_t)OUT_F * IN_F];
__device__ __align__(16) __nv_bfloat16 g_ml[(size_t)OUT_F * IN_F];
__device__ float g_knorm[OUT_F];
__device__ float g_xnorm[NROWS];

__device__ __forceinline__ float softplus_f(float x) {
    return fmaxf(x, 0.0f) + log1pf(expf(-fabsf(x)));
}

__device__ __forceinline__ void cp16(uint32_t sa, const void* gp) {
    asm volatile("cp.async.cg.shared.global [%0], [%1], 16;"
                 :: "r"(sa), "l"(__cvta_generic_to_global(gp)) : "memory");
}
#define CP_COMMIT() asm volatile("cp.async.commit_group;" ::: "memory")
#define CP_WAIT1()  asm volatile("cp.async.wait_group 1;" ::: "memory")

__device__ __forceinline__ uint32_t smem_u32(const void* p) {
    uint32_t a;
    asm("{ .reg .u64 t; cvta.to.shared.u64 t, %1; cvt.u32.u64 %0, t; }" : "=r"(a) : "l"(p));
    return a;
}

__device__ __forceinline__ void ldsm_x4(uint32_t* r, uint32_t addr) {
    asm volatile("ldmatrix.sync.aligned.m8n8.x4.shared.b16 {%0,%1,%2,%3}, [%4];"
                 : "=r"(r[0]), "=r"(r[1]), "=r"(r[2]), "=r"(r[3]) : "r"(addr));
}

__device__ __forceinline__ void mma16816(float* d, const uint32_t* a, const uint32_t* b) {
    asm volatile("mma.sync.aligned.m16n8k16.row.col.f32.bf16.bf16.f32 "
                 "{%0,%1,%2,%3}, {%4,%5,%6,%7}, {%8,%9}, {%0,%1,%2,%3};"
                 : "+f"(d[0]), "+f"(d[1]), "+f"(d[2]), "+f"(d[3])
                 : "r"(a[0]), "r"(a[1]), "r"(a[2]), "r"(a[3]), "r"(b[0]), "r"(b[1]));
}

// ---------------------------------------------------------------------------
// Prep 1: keys = muw*softplus(sgw); knorm; split keys & muw into bf16 hi/lo.
// ---------------------------------------------------------------------------
__global__ __launch_bounds__(256) void prep_w(const float* __restrict__ muw,
                                              const float* __restrict__ sgw) {
    const int row = blockIdx.x;
    const int t = threadIdx.x;
    const size_t base = (size_t)row * IN_F + t * 8;
    float k[8], m[8];
    float4 m0 = *(const float4*)(muw + base);
    float4 m1 = *(const float4*)(muw + base + 4);
    float4 s0 = *(const float4*)(sgw + base);
    float4 s1 = *(const float4*)(sgw + base + 4);
    m[0]=m0.x; m[1]=m0.y; m[2]=m0.z; m[3]=m0.w; m[4]=m1.x; m[5]=m1.y; m[6]=m1.z; m[7]=m1.w;
    float s[8] = {s0.x,s0.y,s0.z,s0.w,s1.x,s1.y,s1.z,s1.w};
    float ss = 0.0f;
    #pragma unroll
    for (int j = 0; j < 8; j++) { k[j] = m[j] * softplus_f(s[j]); ss += k[j]*k[j]; }
    #pragma unroll
    for (int j = 0; j < 8; j += 2) {
        __nv_bfloat16 kh0 = __float2bfloat16(k[j]),   kh1 = __float2bfloat16(k[j+1]);
        __nv_bfloat16 kl0 = __float2bfloat16(k[j]   - __bfloat162float(kh0));
        __nv_bfloat16 kl1 = __float2bfloat16(k[j+1] - __bfloat162float(kh1));
        __nv_bfloat16 mh0 = __float2bfloat16(m[j]),   mh1 = __float2bfloat16(m[j+1]);
        __nv_bfloat16 ml0 = __float2bfloat16(m[j]   - __bfloat162float(mh0));
        __nv_bfloat16 ml1 = __float2bfloat16(m[j+1] - __bfloat162float(mh1));
        *(__nv_bfloat162*)(g_kh + base + j) = __nv_bfloat162(kh0, kh1);
        *(__nv_bfloat162*)(g_kl + base + j) = __nv_bfloat162(kl0, kl1);
        *(__nv_bfloat162*)(g_mh + base + j) = __nv_bfloat162(mh0, mh1);
        *(__nv_bfloat162*)(g_ml + base + j) = __nv_bfloat162(ml0, ml1);
    }
    __shared__ float red[256];
    red[t] = ss;
    __syncthreads();
    for (int st = 128; st > 0; st >>= 1) {
        if (t < st) red[t] += red[t + st];
        __syncthreads();
    }
    if (t == 0) g_knorm[row] = sqrtf(red[0]);
}

// ---------------------------------------------------------------------------
// Prep 2: xnorm; split x into bf16 hi/lo.
// ---------------------------------------------------------------------------
__global__ __launch_bounds__(256) void prep_x(const float* __restrict__ x) {
    const int row = blockIdx.x;
    const int t = threadIdx.x;
    const size_t base = (size_t)row * IN_F + t * 8;
    float4 v0 = *(const float4*)(x + base);
    float4 v1 = *(const float4*)(x + base + 4);
    float v[8] = {v0.x,v0.y,v0.z,v0.w,v1.x,v1.y,v1.z,v1.w};
    float ss = 0.0f;
    #pragma unroll
    for (int j = 0; j < 8; j++) ss += v[j]*v[j];
    #pragma unroll
    for (int j = 0; j < 8; j += 2) {
        __nv_bfloat16 h0 = __float2bfloat16(v[j]),   h1 = __float2bfloat16(v[j+1]);
        __nv_bfloat16 l0 = __float2bfloat16(v[j]   - __bfloat162float(h0));
        __nv_bfloat16 l1 = __float2bfloat16(v[j+1] - __bfloat162float(h1));
        *(__nv_bfloat162*)(g_xh + base + j) = __nv_bfloat162(h0, h1);
        *(__nv_bfloat162*)(g_xl + base + j) = __nv_bfloat162(l0, l1);
    }
    __shared__ float red[256];
    red[t] = ss;
    __syncthreads();
    for (int st = 128; st > 0; st >>= 1) {
        if (t < st) red[t] += red[t + st];
        __syncthreads();
    }
    if (t == 0) g_xnorm[row] = sqrtf(red[0]);
}

// ---------------------------------------------------------------------------
// Main mma.sync kernel: CTA 128x128, 8 warps (4 in M, 2 in N), warp 32x64.
// dots = xh*kh + xh*kl + xl*kh; comp = xh*mh + xh*ml + xl*mh. fp32 accum.
// BK=32, 3-stage cp.async pipeline, ldmatrix operand loads.
// ---------------------------------------------------------------------------
#define BK      32
#define LDT     40                        // padded row len (bf16); conflict-free
#define TILE_E  (128 * LDT)               // elems per operand tile
#define TILE_B  (TILE_E * 2)              // 10240 bytes
#define STAGE_B (6 * TILE_B)              // 61440 bytes
#define NIT     (IN_F / BK)               // 64
#define SMEM_SZ (3 * STAGE_B)             // 184320  (epilogue reuses 128KB of it)

__global__ __launch_bounds__(256, 1)
void moie_mma_kernel(const float* __restrict__ gate,
                     const float* __restrict__ bias,
                     float* __restrict__ out) {
    extern __shared__ char smem[];
    const uint32_t sbase = smem_u32(smem);
    const int tid  = threadIdx.x;
    const int warp = tid >> 5;
    const int lane = tid & 31;
    const int wm   = warp >> 1;          // 0..3 (M, 32 rows)
    const int wn   = warp & 1;           // 0..1 (N, 64 cols)
    const int mBase = blockIdx.y * 128;
    const int nBase = blockIdx.x * 128;

    const __nv_bfloat16* gsrc[6] = { g_xh, g_xl, g_kh, g_kl, g_mh, g_ml };
    const int            grow[6] = { mBase, mBase, nBase, nBase, nBase, nBase };

    float accD[2][8][4];   // dots: 2 m16 x 8 n8
    float accC[2][8][4];   // comp
    #pragma unroll
    for (int i = 0; i < 2; i++)
        #pragma unroll
        for (int j = 0; j < 8; j++)
            #pragma unroll
            for (int q = 0; q < 4; q++) { accD[i][j][q] = 0.0f; accC[i][j][q] = 0.0f; }

    // per-lane ldmatrix offsets (bytes), within a tile
    // A (x4 over 16x16): row=(lane&15), kofs=(lane>>4)*8 elems
    const uint32_t aOff = ((lane & 15) * LDT + (lane >> 4) * 8) * 2;
    // B (x4 over n16 x k16): row=(lane&7)+((lane&16)>>1), kofs=((lane>>3)&1)*8
    const uint32_t bOff = (((lane & 7) | ((lane & 16) >> 1)) * LDT + ((lane >> 3) & 1) * 8) * 2;

    auto load_stage = [&](int slot, int it) {
        const uint32_t sb = sbase + (uint32_t)slot * STAGE_B;
        const int k0 = it * BK;
        #pragma unroll
        for (int tl = 0; tl < 6; ++tl) {
            const uint32_t tb = sb + tl * TILE_B;
            const __nv_bfloat16* gp = gsrc[tl];
            const int rb = grow[tl];
            #pragma unroll
            for (int t = 0; t < 2; ++t) {
                const int v   = tid + t * 256;      // 0..511
                const int row = v >> 2;             // 0..127
                const int c16 = v & 3;              // 16B chunk
                cp16(tb + row * (LDT * 2) + c16 * 16,
                     gp + (size_t)(rb + row) * IN_F + k0 + c16 * 8);
            }
        }
    };

    load_stage(0, 0); CP_COMMIT();
    load_stage(1, 1); CP_COMMIT();

    for (int it = 0; it < NIT; ++it) {
        CP_WAIT1();
        __syncthreads();

        // prefetch stage it+2 (slot reuse is safe: barrier above means all
        // warps finished computing iteration it-1, which used this slot)
        if (it + 2 < NIT) load_stage((it + 2) % 3, it + 2);
        CP_COMMIT();

        const uint32_t st = sbase + (uint32_t)(it % 3) * STAGE_B;
        const uint32_t Axh = st;
        const uint32_t Axl = st + 1 * TILE_B;
        const uint32_t Bkh = st + 2 * TILE_B;
        const uint32_t Bkl = st + 3 * TILE_B;
        const uint32_t Bmh = st + 4 * TILE_B;
        const uint32_t Bml = st + 5 * TILE_B;
        const uint32_t aWarp = (uint32_t)(wm * 32) * (LDT * 2);
        const uint32_t bWarp = (uint32_t)(wn * 64) * (LDT * 2);

        #pragma unroll
        for (int ks = 0; ks < BK / 16; ++ks) {
            const uint32_t kB = ks * 32;            // 16 elems * 2B
            uint32_t ah[2][4], al[2][4];
            #pragma unroll
            for (int mi = 0; mi < 2; ++mi) {
                ldsm_x4(ah[mi], Axh + aWarp + (uint32_t)(mi * 16) * (LDT * 2) + kB + aOff);
                ldsm_x4(al[mi], Axl + aWarp + (uint32_t)(mi * 16) * (LDT * 2) + kB + aOff);
            }
            uint32_t b[8][2];
            // ---- kh: dots += xh*kh + xl*kh ----
            #pragma unroll
            for (int nt = 0; nt < 4; ++nt) {
                uint32_t r[4];
                ldsm_x4(r, Bkh + bWarp + (uint32_t)(nt * 16) * (LDT * 2) + kB + bOff);
                b[nt*2][0] = r[0]; b[nt*2][1] = r[1]; b[nt*2+1][0] = r[2]; b[nt*2+1][1] = r[3];
            }
            #pragma unroll
            for (int mi = 0; mi < 2; ++mi)
                #pragma unroll
                for (int ni = 0; ni < 8; ++ni) {
                    mma16816(accD[mi][ni], ah[mi], b[ni]);
                    mma16816(accD[mi][ni], al[mi], b[ni]);
                }
            // ---- kl: dots += xh*kl ----
            #pragma unroll
            for (int nt = 0; nt < 4; ++nt) {
                uint32_t r[4];
                ldsm_x4(r, Bkl + bWarp + (uint32_t)(nt * 16) * (LDT * 2) + kB + bOff);
                b[nt*2][0] = r[0]; b[nt*2][1] = r[1]; b[nt*2+1][0] = r[2]; b[nt*2+1][1] = r[3];
            }
            #pragma unroll
            for (int mi = 0; mi < 2; ++mi)
                #pragma unroll
                for (int ni = 0; ni < 8; ++ni)
                    mma16816(accD[mi][ni], ah[mi], b[ni]);
            // ---- mh: comp += xh*mh + xl*mh ----
            #pragma unroll
            for (int nt = 0; nt < 4; ++nt) {
                uint32_t r[4];
                ldsm_x4(r, Bmh + bWarp + (uint32_t)(nt * 16) * (LDT * 2) + kB + bOff);
                b[nt*2][0] = r[0]; b[nt*2][1] = r[1]; b[nt*2+1][0] = r[2]; b[nt*2+1][1] = r[3];
            }
            #pragma unroll
            for (int mi = 0; mi < 2; ++mi)
                #pragma unroll
                for (int ni = 0; ni < 8; ++ni) {
                    mma16816(accC[mi][ni], ah[mi], b[ni]);
                    mma16816(accC[mi][ni], al[mi], b[ni]);
                }
            // ---- ml: comp += xh*ml ----
            #pragma unroll
            for (int nt = 0; nt < 4; ++nt) {
                uint32_t r[4];
                ldsm_x4(r, Bml + bWarp + (uint32_t)(nt * 16) * (LDT * 2) + kB + bOff);
                b[nt*2][0] = r[0]; b[nt*2][1] = r[1]; b[nt*2+1][0] = r[2]; b[nt*2+1][1] = r[3];
            }
            #pragma unroll
            for (int mi = 0; mi < 2; ++mi)
                #pragma unroll
                for (int ni = 0; ni < 8; ++ni)
                    mma16816(accC[mi][ni], ah[mi], b[ni]);
        }
        __syncthreads();
    }

    // ---- epilogue: frags -> SMEM (row-major), then fused scalar pass ----
    float* sD = (float*)smem;            // 128x128 dots
    float* sC = sD + 128 * 128;          // 128x128 comp
    {
        const int r0 = wm * 32 + (lane >> 2);
        const int c0 = wn * 64 + (lane & 3) * 2;
        #pragma unroll
        for (int mi = 0; mi < 2; ++mi)
            #pragma unroll
            for (int ni = 0; ni < 8; ++ni) {
                const int r = r0 + mi * 16;
                const int c = c0 + ni * 8;
                *(float2*)(sD + r * 128 + c)       = make_float2(accD[mi][ni][0], accD[mi][ni][1]);
                *(float2*)(sD + (r + 8) * 128 + c) = make_float2(accD[mi][ni][2], accD[mi][ni][3]);
                *(float2*)(sC + r * 128 + c)       = make_float2(accC[mi][ni][0], accC[mi][ni][1]);
                *(float2*)(sC + (r + 8) * 128 + c) = make_float2(accC[mi][ni][2], accC[mi][ni][3]);
            }
    }
    __syncthreads();

    const size_t NO = (size_t)NROWS * OUT_F;
    #pragma unroll
    for (int e = 0; e < 16; ++e) {
        const int lin = e * 256 + tid;       // float4 index
        const int row = lin >> 5;
        const int c4  = (lin & 31) * 4;
        const int m   = mBase + row;
        const float xn = g_xnorm[m];
        float4 d = *(float4*)(sD + row * 128 + c4);
        float4 c = *(float4*)(sC + row * 128 + c4);
        float sc[4], mk[4];
        const float* dv = &d.x;
        const float* cv = &c.x;
        #pragma unroll
        for (int j = 0; j < 4; ++j) {
            const int n = nBase + c4 + j;
            const float score = dv[j] / fmaxf(xn * g_knorm[n], 1e-8f);
            const float w = fmaxf(score - gate[n], 0.0f);
            sc[j] = score;
            mk[j] = (cv[j] + bias[n]) * w;
        }
        float4 sc4 = make_float4(sc[0], sc[1], sc[2], sc[3]);
        float4 mk4 = make_float4(mk[0], mk[1], mk[2], mk[3]);
        const size_t idx = (size_t)m * OUT_F + nBase + c4;
        *(float4*)(out + idx)          = mk4;   // output
        *(float4*)(out + NO + idx)     = sc4;   // scores
        *(float4*)(out + 2 * NO + idx) = mk4;   // masked
    }
}

// ---------------------------------------------------------------------------
extern "C" void kernel_launch(void* const* d_in, const int* in_sizes, int n_in,
                              void* d_out, int out_size) {
    const float* x    = (const float*)d_in[0];
    const float* muw  = (const float*)d_in[1];
    const float* sgw  = (const float*)d_in[2];
    const float* gate = (const float*)d_in[3];
    const float* bias = (const float*)d_in[4];
    float* out = (float*)d_out;

    cudaFuncSetAttribute(moie_mma_kernel, cudaFuncAttributeMaxDynamicSharedMemorySize, SMEM_SZ);

    prep_w<<<OUT_F, 256>>>(muw, sgw);
    prep_x<<<NROWS, 256>>>(x);
    dim3 grid(OUT_F / 128, NROWS / 128);
    moie_mma_kernel<<<grid, 256, SMEM_SZ>>>(gate, bias, out);
}

// round 6
// speedup vs baseline: 4.5417x; 1.1627x over previous
#include <cuda_runtime.h>
#include <cuda_fp16.h>
#include <math.h>
#include <stdint.h>

#define IN_F  2048
#define OUT_F 2048
#define NROWS 8192   // 4 * 2048

// ---------------------------------------------------------------------------
// Scratch (__device__ globals; no runtime allocation allowed)
// ---------------------------------------------------------------------------
__device__ __align__(16) __half g_xh[(size_t)NROWS * IN_F];
__device__ __align__(16) __half g_xl[(size_t)NROWS * IN_F];
__device__ __align__(16) __half g_kh[(size_t)OUT_F * IN_F];
__device__ __align__(16) __half g_kl[(size_t)OUT_F * IN_F];
__device__ __align__(16) __half g_mh[(size_t)OUT_F * IN_F];
__device__ float g_knorm[OUT_F];
__device__ float g_xnorm[NROWS];

__device__ __forceinline__ float softplus_f(float x) {
    return fmaxf(x, 0.0f) + log1pf(expf(-fabsf(x)));
}

__device__ __forceinline__ void cp16(uint32_t sa, const void* gp) {
    asm volatile("cp.async.cg.shared.global [%0], [%1], 16;"
                 :: "r"(sa), "l"(__cvta_generic_to_global(gp)) : "memory");
}
#define CP_COMMIT() asm volatile("cp.async.commit_group;" ::: "memory")
#define CP_WAIT1()  asm volatile("cp.async.wait_group 1;" ::: "memory")

__device__ __forceinline__ uint32_t smem_u32(const void* p) {
    uint32_t a;
    asm("{ .reg .u64 t; cvta.to.shared.u64 t, %1; cvt.u32.u64 %0, t; }" : "=r"(a) : "l"(p));
    return a;
}

__device__ __forceinline__ void ldsm_x4(uint32_t* r, uint32_t addr) {
    asm volatile("ldmatrix.sync.aligned.m8n8.x4.shared.b16 {%0,%1,%2,%3}, [%4];"
                 : "=r"(r[0]), "=r"(r[1]), "=r"(r[2]), "=r"(r[3]) : "r"(addr));
}

__device__ __forceinline__ void mma16816(float* d, const uint32_t* a, const uint32_t* b) {
    asm volatile("mma.sync.aligned.m16n8k16.row.col.f32.f16.f16.f32 "
                 "{%0,%1,%2,%3}, {%4,%5,%6,%7}, {%8,%9}, {%0,%1,%2,%3};"
                 : "+f"(d[0]), "+f"(d[1]), "+f"(d[2]), "+f"(d[3])
                 : "r"(a[0]), "r"(a[1]), "r"(a[2]), "r"(a[3]), "r"(b[0]), "r"(b[1]));
}

// ---------------------------------------------------------------------------
// Prep 1: keys = muw*softplus(sgw); knorm; fp16 hi/lo of keys, fp16 hi of muw
// plus fp16 lo NOT needed for muw (comp is 2-term). grid=OUT_F, 256 thr.
// ---------------------------------------------------------------------------
__global__ __launch_bounds__(256) void prep_w(const float* __restrict__ muw,
                                              const float* __restrict__ sgw) {
    const int row = blockIdx.x;
    const int t = threadIdx.x;
    const size_t base = (size_t)row * IN_F + t * 8;
    float k[8], m[8];
    float4 m0 = *(const float4*)(muw + base);
    float4 m1 = *(const float4*)(muw + base + 4);
    float4 s0 = *(const float4*)(sgw + base);
    float4 s1 = *(const float4*)(sgw + base + 4);
    m[0]=m0.x; m[1]=m0.y; m[2]=m0.z; m[3]=m0.w; m[4]=m1.x; m[5]=m1.y; m[6]=m1.z; m[7]=m1.w;
    float s[8] = {s0.x,s0.y,s0.z,s0.w,s1.x,s1.y,s1.z,s1.w};
    float ss = 0.0f;
    #pragma unroll
    for (int j = 0; j < 8; j++) { k[j] = m[j] * softplus_f(s[j]); ss += k[j]*k[j]; }
    #pragma unroll
    for (int j = 0; j < 8; j += 2) {
        __half kh0 = __float2half(k[j]),   kh1 = __float2half(k[j+1]);
        __half kl0 = __float2half(k[j]   - __half2float(kh0));
        __half kl1 = __float2half(k[j+1] - __half2float(kh1));
        __half mh0 = __float2half(m[j]),   mh1 = __float2half(m[j+1]);
        *(__half2*)(g_kh + base + j) = __half2(kh0, kh1);
        *(__half2*)(g_kl + base + j) = __half2(kl0, kl1);
        *(__half2*)(g_mh + base + j) = __half2(mh0, mh1);
    }
    __shared__ float red[256];
    red[t] = ss;
    __syncthreads();
    for (int st = 128; st > 0; st >>= 1) {
        if (t < st) red[t] += red[t + st];
        __syncthreads();
    }
    if (t == 0) g_knorm[row] = sqrtf(red[0]);
}

// ---------------------------------------------------------------------------
// Prep 2: xnorm; fp16 hi/lo split of x. grid = NROWS.
// ---------------------------------------------------------------------------
__global__ __launch_bounds__(256) void prep_x(const float* __restrict__ x) {
    const int row = blockIdx.x;
    const int t = threadIdx.x;
    const size_t base = (size_t)row * IN_F + t * 8;
    float4 v0 = *(const float4*)(x + base);
    float4 v1 = *(const float4*)(x + base + 4);
    float v[8] = {v0.x,v0.y,v0.z,v0.w,v1.x,v1.y,v1.z,v1.w};
    float ss = 0.0f;
    #pragma unroll
    for (int j = 0; j < 8; j++) ss += v[j]*v[j];
    #pragma unroll
    for (int j = 0; j < 8; j += 2) {
        __half h0 = __float2half(v[j]),   h1 = __float2half(v[j+1]);
        __half l0 = __float2half(v[j]   - __half2float(h0));
        __half l1 = __float2half(v[j+1] - __half2float(h1));
        *(__half2*)(g_xh + base + j) = __half2(h0, h1);
        *(__half2*)(g_xl + base + j) = __half2(l0, l1);
    }
    __shared__ float red[256];
    red[t] = ss;
    __syncthreads();
    for (int st = 128; st > 0; st >>= 1) {
        if (t < st) red[t] += red[t + st];
        __syncthreads();
    }
    if (t == 0) g_xnorm[row] = sqrtf(red[0]);
}

// ---------------------------------------------------------------------------
// Main mma.sync kernel: CTA 128x128, 8 warps (4 in M, 2 in N), warp 32x64.
// dots = xh*kh + xh*kl + xl*kh  (fp16 3-term, err ~2^-24)
// comp = xh*mh + xl*mh = x*mh   (fp16 2-term, err ~2^-12)
// BK=32, 3-stage cp.async pipeline, ldmatrix, one barrier/iter.
// ---------------------------------------------------------------------------
#define BK      32
#define LDT     40                        // padded row len (fp16); conflict-free
#define TILE_B  (128 * LDT * 2)           // 10240 bytes
#define NTILES  5                         // xh xl kh kl mh
#define STAGE_B (NTILES * TILE_B)         // 51200 bytes
#define NIT     (IN_F / BK)               // 64
#define SMEM_SZ (3 * STAGE_B)             // 153600 (epilogue reuses 128KB)

__global__ __launch_bounds__(256, 1)
void moie_mma_kernel(const float* __restrict__ gate,
                     const float* __restrict__ bias,
                     float* __restrict__ out) {
    extern __shared__ char smem[];
    const uint32_t sbase = smem_u32(smem);
    const int tid  = threadIdx.x;
    const int warp = tid >> 5;
    const int lane = tid & 31;
    const int wm   = warp >> 1;          // 0..3 (M, 32 rows)
    const int wn   = warp & 1;           // 0..1 (N, 64 cols)
    const int mBase = blockIdx.y * 128;
    const int nBase = blockIdx.x * 128;

    const __half* gsrc[NTILES] = { g_xh, g_xl, g_kh, g_kl, g_mh };
    const int     grow[NTILES] = { mBase, mBase, nBase, nBase, nBase };

    float accD[2][8][4];
    float accC[2][8][4];
    #pragma unroll
    for (int i = 0; i < 2; i++)
        #pragma unroll
        for (int j = 0; j < 8; j++)
            #pragma unroll
            for (int q = 0; q < 4; q++) { accD[i][j][q] = 0.0f; accC[i][j][q] = 0.0f; }

    const uint32_t aOff = ((lane & 15) * LDT + (lane >> 4) * 8) * 2;
    const uint32_t bOff = (((lane & 7) | ((lane & 16) >> 1)) * LDT + ((lane >> 3) & 1) * 8) * 2;

    auto load_stage = [&](int slot, int it) {
        const uint32_t sb = sbase + (uint32_t)slot * STAGE_B;
        const int k0 = it * BK;
        #pragma unroll
        for (int tl = 0; tl < NTILES; ++tl) {
            const uint32_t tb = sb + tl * TILE_B;
            const __half* gp = gsrc[tl];
            const int rb = grow[tl];
            #pragma unroll
            for (int t = 0; t < 2; ++t) {
                const int v   = tid + t * 256;      // 0..511
                const int row = v >> 2;             // 0..127
                const int c16 = v & 3;              // 16B chunk
                cp16(tb + row * (LDT * 2) + c16 * 16,
                     gp + (size_t)(rb + row) * IN_F + k0 + c16 * 8);
            }
        }
    };

    load_stage(0, 0); CP_COMMIT();
    load_stage(1, 1); CP_COMMIT();

    for (int it = 0; it < NIT; ++it) {
        CP_WAIT1();
        __syncthreads();
        // Single barrier/iter: at this point every warp has finished iter it-1,
        // so slot (it+2)%3 == (it-1)%3 has no readers left -> safe to refill.
        if (it + 2 < NIT) load_stage((it + 2) % 3, it + 2);
        CP_COMMIT();

        const uint32_t st = sbase + (uint32_t)(it % 3) * STAGE_B;
        const uint32_t Axh = st;
        const uint32_t Axl = st + 1 * TILE_B;
        const uint32_t Bkh = st + 2 * TILE_B;
        const uint32_t Bkl = st + 3 * TILE_B;
        const uint32_t Bmh = st + 4 * TILE_B;
        const uint32_t aWarp = (uint32_t)(wm * 32) * (LDT * 2);
        const uint32_t bWarp = (uint32_t)(wn * 64) * (LDT * 2);

        #pragma unroll
        for (int ks = 0; ks < BK / 16; ++ks) {
            const uint32_t kB = ks * 32;
            uint32_t ah[2][4], al[2][4];
            #pragma unroll
            for (int mi = 0; mi < 2; ++mi) {
                ldsm_x4(ah[mi], Axh + aWarp + (uint32_t)(mi * 16) * (LDT * 2) + kB + aOff);
                ldsm_x4(al[mi], Axl + aWarp + (uint32_t)(mi * 16) * (LDT * 2) + kB + aOff);
            }
            uint32_t b[8][2];
            // ---- kh: dots += xh*kh + xl*kh ----
            #pragma unroll
            for (int nt = 0; nt < 4; ++nt) {
                uint32_t r[4];
                ldsm_x4(r, Bkh + bWarp + (uint32_t)(nt * 16) * (LDT * 2) + kB + bOff);
                b[nt*2][0] = r[0]; b[nt*2][1] = r[1]; b[nt*2+1][0] = r[2]; b[nt*2+1][1] = r[3];
            }
            #pragma unroll
            for (int mi = 0; mi < 2; ++mi)
                #pragma unroll
                for (int ni = 0; ni < 8; ++ni) {
                    mma16816(accD[mi][ni], ah[mi], b[ni]);
                    mma16816(accD[mi][ni], al[mi], b[ni]);
                }
            // ---- kl: dots += xh*kl ----
            #pragma unroll
            for (int nt = 0; nt < 4; ++nt) {
                uint32_t r[4];
                ldsm_x4(r, Bkl + bWarp + (uint32_t)(nt * 16) * (LDT * 2) + kB + bOff);
                b[nt*2][0] = r[0]; b[nt*2][1] = r[1]; b[nt*2+1][0] = r[2]; b[nt*2+1][1] = r[3];
            }
            #pragma unroll
            for (int mi = 0; mi < 2; ++mi)
                #pragma unroll
                for (int ni = 0; ni < 8; ++ni)
                    mma16816(accD[mi][ni], ah[mi], b[ni]);
            // ---- mh: comp += xh*mh + xl*mh ----
            #pragma unroll
            for (int nt = 0; nt < 4; ++nt) {
                uint32_t r[4];
                ldsm_x4(r, Bmh + bWarp + (uint32_t)(nt * 16) * (LDT * 2) + kB + bOff);
                b[nt*2][0] = r[0]; b[nt*2][1] = r[1]; b[nt*2+1][0] = r[2]; b[nt*2+1][1] = r[3];
            }
            #pragma unroll
            for (int mi = 0; mi < 2; ++mi)
                #pragma unroll
                for (int ni = 0; ni < 8; ++ni) {
                    mma16816(accC[mi][ni], ah[mi], b[ni]);
                    mma16816(accC[mi][ni], al[mi], b[ni]);
                }
        }
        __syncthreads();
    }

    // ---- epilogue: frags -> SMEM (row-major), then fused scalar pass ----
    float* sD = (float*)smem;            // 128x128 dots
    float* sC = sD + 128 * 128;          // 128x128 comp
    {
        const int r0 = wm * 32 + (lane >> 2);
        const int c0 = wn * 64 + (lane & 3) * 2;
        #pragma unroll
        for (int mi = 0; mi < 2; ++mi)
            #pragma unroll
            for (int ni = 0; ni < 8; ++ni) {
                const int r = r0 + mi * 16;
                const int c = c0 + ni * 8;
                *(float2*)(sD + r * 128 + c)       = make_float2(accD[mi][ni][0], accD[mi][ni][1]);
                *(float2*)(sD + (r + 8) * 128 + c) = make_float2(accD[mi][ni][2], accD[mi][ni][3]);
                *(float2*)(sC + r * 128 + c)       = make_float2(accC[mi][ni][0], accC[mi][ni][1]);
                *(float2*)(sC + (r + 8) * 128 + c) = make_float2(accC[mi][ni][2], accC[mi][ni][3]);
            }
    }
    __syncthreads();

    const size_t NO = (size_t)NROWS * OUT_F;
    #pragma unroll
    for (int e = 0; e < 16; ++e) {
        const int lin = e * 256 + tid;
        const int row = lin >> 5;
        const int c4  = (lin & 31) * 4;
        const int m   = mBase + row;
        const float xn = g_xnorm[m];
        float4 d = *(float4*)(sD + row * 128 + c4);
        float4 c = *(float4*)(sC + row * 128 + c4);
        float sc[4], mk[4];
        const float* dv = &d.x;
        const float* cv = &c.x;
        #pragma unroll
        for (int j = 0; j < 4; ++j) {
            const int n = nBase + c4 + j;
            const float score = dv[j] / fmaxf(xn * g_knorm[n], 1e-8f);
            const float w = fmaxf(score - gate[n], 0.0f);
            sc[j] = score;
            mk[j] = (cv[j] + bias[n]) * w;
        }
        float4 sc4 = make_float4(sc[0], sc[1], sc[2], sc[3]);
        float4 mk4 = make_float4(mk[0], mk[1], mk[2], mk[3]);
        const size_t idx = (size_t)m * OUT_F + nBase + c4;
        *(float4*)(out + idx)          = mk4;   // output
        *(float4*)(out + NO + idx)     = sc4;   // scores
        *(float4*)(out + 2 * NO + idx) = mk4;   // masked
    }
}

// ---------------------------------------------------------------------------
extern "C" void kernel_launch(void* const* d_in, const int* in_sizes, int n_in,
                              void* d_out, int out_size) {
    const float* x    = (const float*)d_in[0];
    const float* muw  = (const float*)d_in[1];
    const float* sgw  = (const float*)d_in[2];
    const float* gate = (const float*)d_in[3];
    const float* bias = (const float*)d_in[4];
    float* out = (float*)d_out;

    cudaFuncSetAttribute(moie_mma_kernel, cudaFuncAttributeMaxDynamicSharedMemorySize, SMEM_SZ);

    prep_w<<<OUT_F, 256>>>(muw, sgw);
    prep_x<<<NROWS, 256>>>(x);
    dim3 grid(OUT_F / 128, NROWS / 128);
    moie_mma_kernel<<<grid, 256, SMEM_SZ>>>(gate, bias, out);
}

// round 9
// speedup vs baseline: 5.4872x; 1.2082x over previous
#include <cuda_runtime.h>
#include <cuda_fp16.h>
#include <math.h>
#include <stdint.h>

#define IN_F  2048
#define OUT_F 2048
#define NROWS 8192   // 4 * 2048

// ---------------------------------------------------------------------------
// Scratch (__device__ globals; no runtime allocation allowed)
// ---------------------------------------------------------------------------
__device__ __align__(16) __half g_xh[(size_t)NROWS * IN_F];
__device__ __align__(16) __half g_xl[(size_t)NROWS * IN_F];
__device__ __align__(16) __half g_kh[(size_t)OUT_F * IN_F];
__device__ __align__(16) __half g_mh[(size_t)OUT_F * IN_F];
__device__ float g_knorm[OUT_F];
__device__ float g_xnorm[NROWS];

__device__ __forceinline__ float softplus_f(float x) {
    return fmaxf(x, 0.0f) + log1pf(expf(-fabsf(x)));
}

__device__ __forceinline__ void cp16(uint32_t sa, const void* gp) {
    asm volatile("cp.async.cg.shared.global [%0], [%1], 16;"
                 :: "r"(sa), "l"(__cvta_generic_to_global(gp)) : "memory");
}
#define CP_COMMIT() asm volatile("cp.async.commit_group;" ::: "memory")
#define CP_WAIT1()  asm volatile("cp.async.wait_group 1;" ::: "memory")

__device__ __forceinline__ uint32_t smem_u32(const void* p) {
    uint32_t a;
    asm("{ .reg .u64 t; cvta.to.shared.u64 t, %1; cvt.u32.u64 %0, t; }" : "=r"(a) : "l"(p));
    return a;
}

__device__ __forceinline__ void ldsm_x4(uint32_t* r, uint32_t addr) {
    asm volatile("ldmatrix.sync.aligned.m8n8.x4.shared.b16 {%0,%1,%2,%3}, [%4];"
                 : "=r"(r[0]), "=r"(r[1]), "=r"(r[2]), "=r"(r[3]) : "r"(addr));
}

__device__ __forceinline__ void mma16816(float* d, const uint32_t* a, const uint32_t* b) {
    asm volatile("mma.sync.aligned.m16n8k16.row.col.f32.f16.f16.f32 "
                 "{%0,%1,%2,%3}, {%4,%5,%6,%7}, {%8,%9}, {%0,%1,%2,%3};"
                 : "+f"(d[0]), "+f"(d[1]), "+f"(d[2]), "+f"(d[3])
                 : "r"(a[0]), "r"(a[1]), "r"(a[2]), "r"(a[3]), "r"(b[0]), "r"(b[1]));
}

// ---------------------------------------------------------------------------
// Prep 1: keys = muw*softplus(sgw); knorm (from exact keys); store fp16 kh, mh.
// grid = OUT_F, 256 threads, 8 elements/thread.
// ---------------------------------------------------------------------------
__global__ __launch_bounds__(256) void prep_w(const float* __restrict__ muw,
                                              const float* __restrict__ sgw) {
    const int row = blockIdx.x;
    const int t = threadIdx.x;
    const size_t base = (size_t)row * IN_F + t * 8;
    float k[8], m[8];
    float4 m0 = *(const float4*)(muw + base);
    float4 m1 = *(const float4*)(muw + base + 4);
    float4 s0 = *(const float4*)(sgw + base);
    float4 s1 = *(const float4*)(sgw + base + 4);
    m[0]=m0.x; m[1]=m0.y; m[2]=m0.z; m[3]=m0.w; m[4]=m1.x; m[5]=m1.y; m[6]=m1.z; m[7]=m1.w;
    float s[8] = {s0.x,s0.y,s0.z,s0.w,s1.x,s1.y,s1.z,s1.w};
    float ss = 0.0f;
    #pragma unroll
    for (int j = 0; j < 8; j++) { k[j] = m[j] * softplus_f(s[j]); ss += k[j]*k[j]; }
    #pragma unroll
    for (int j = 0; j < 8; j += 2) {
        *(__half2*)(g_kh + base + j) = __half2(__float2half(k[j]), __float2half(k[j+1]));
        *(__half2*)(g_mh + base + j) = __half2(__float2half(m[j]), __float2half(m[j+1]));
    }
    __shared__ float red[256];
    red[t] = ss;
    __syncthreads();
    for (int st = 128; st > 0; st >>= 1) {
        if (t < st) red[t] += red[t + st];
        __syncthreads();
    }
    if (t == 0) g_knorm[row] = sqrtf(red[0]);
}

// ---------------------------------------------------------------------------
// Prep 2: xnorm; fp16 hi/lo split of x. grid = NROWS.
// ---------------------------------------------------------------------------
__global__ __launch_bounds__(256) void prep_x(const float* __restrict__ x) {
    const int row = blockIdx.x;
    const int t = threadIdx.x;
    const size_t base = (size_t)row * IN_F + t * 8;
    float4 v0 = *(const float4*)(x + base);
    float4 v1 = *(const float4*)(x + base + 4);
    float v[8] = {v0.x,v0.y,v0.z,v0.w,v1.x,v1.y,v1.z,v1.w};
    float ss = 0.0f;
    #pragma unroll
    for (int j = 0; j < 8; j++) ss += v[j]*v[j];
    #pragma unroll
    for (int j = 0; j < 8; j += 2) {
        __half h0 = __float2half(v[j]),   h1 = __float2half(v[j+1]);
        __half l0 = __float2half(v[j]   - __half2float(h0));
        __half l1 = __float2half(v[j+1] - __half2float(h1));
        *(__half2*)(g_xh + base + j) = __half2(h0, h1);
        *(__half2*)(g_xl + base + j) = __half2(l0, l1);
    }
    __shared__ float red[256];
    red[t] = ss;
    __syncthreads();
    for (int st = 128; st > 0; st >>= 1) {
        if (t < st) red[t] += red[t + st];
        __syncthreads();
    }
    if (t == 0) g_xnorm[row] = sqrtf(red[0]);
}

// ---------------------------------------------------------------------------
// Main mma.sync kernel: CTA 128x128, 8 warps (4 in M, 2 in N), warp 32x64.
// dots = xh*kh + xl*kh = x*kh   (exact x, err only from fp16 kh ~2^-12)
// comp = xh*mh + xl*mh = x*mh   (exact x, err only from fp16 mh ~2^-12)
// Both GEMMs share the A fragments. BK=32, 3-stage cp.async, ldmatrix.
// ---------------------------------------------------------------------------
#define BK      32
#define LDT     40                        // padded row len (fp16); conflict-free
#define TILE_B  (128 * LDT * 2)           // 10240 bytes
#define NTILES  4                         // xh xl kh mh
#define STAGE_B (NTILES * TILE_B)         // 40960 bytes
#define NIT     (IN_F / BK)               // 64
// SMEM: mainloop needs 3*STAGE_B = 122880; epilogue reuses it as
// 2 x 128x128 fp32 = 131072. Take the max (this was the R7 OOB bug).
#define SMEM_SZ 131072

__global__ __launch_bounds__(256, 1)
void moie_mma_kernel(const float* __restrict__ gate,
                     const float* __restrict__ bias,
                     float* __restrict__ out) {
    extern __shared__ char smem[];
    const uint32_t sbase = smem_u32(smem);
    const int tid  = threadIdx.x;
    const int warp = tid >> 5;
    const int lane = tid & 31;
    const int wm   = warp >> 1;          // 0..3 (M, 32 rows)
    const int wn   = warp & 1;           // 0..1 (N, 64 cols)
    const int mBase = blockIdx.y * 128;
    const int nBase = blockIdx.x * 128;

    const __half* gsrc[NTILES] = { g_xh, g_xl, g_kh, g_mh };
    const int     grow[NTILES] = { mBase, mBase, nBase, nBase };

    float accD[2][8][4];
    float accC[2][8][4];
    #pragma unroll
    for (int i = 0; i < 2; i++)
        #pragma unroll
        for (int j = 0; j < 8; j++)
            #pragma unroll
            for (int q = 0; q < 4; q++) { accD[i][j][q] = 0.0f; accC[i][j][q] = 0.0f; }

    const uint32_t aOff = ((lane & 15) * LDT + (lane >> 4) * 8) * 2;
    const uint32_t bOff = (((lane & 7) | ((lane & 16) >> 1)) * LDT + ((lane >> 3) & 1) * 8) * 2;

    auto load_stage = [&](int slot, int it) {
        const uint32_t sb = sbase + (uint32_t)slot * STAGE_B;
        const int k0 = it * BK;
        #pragma unroll
        for (int tl = 0; tl < NTILES; ++tl) {
            const uint32_t tb = sb + tl * TILE_B;
            const __half* gp = gsrc[tl];
            const int rb = grow[tl];
            #pragma unroll
            for (int t = 0; t < 2; ++t) {
                const int v   = tid + t * 256;      // 0..511
                const int row = v >> 2;             // 0..127
                const int c16 = v & 3;              // 16B chunk
                cp16(tb + row * (LDT * 2) + c16 * 16,
                     gp + (size_t)(rb + row) * IN_F + k0 + c16 * 8);
            }
        }
    };

    load_stage(0, 0); CP_COMMIT();
    load_stage(1, 1); CP_COMMIT();

    for (int it = 0; it < NIT; ++it) {
        CP_WAIT1();
        __syncthreads();
        // Single barrier/iter: every warp has finished iter it-1, so slot
        // (it+2)%3 == (it-1)%3 has no readers left -> safe to refill.
        if (it + 2 < NIT) load_stage((it + 2) % 3, it + 2);
        CP_COMMIT();

        const uint32_t st = sbase + (uint32_t)(it % 3) * STAGE_B;
        const uint32_t Axh = st;
        const uint32_t Axl = st + 1 * TILE_B;
        const uint32_t Bkh = st + 2 * TILE_B;
        const uint32_t Bmh = st + 3 * TILE_B;
        const uint32_t aWarp = (uint32_t)(wm * 32) * (LDT * 2);
        const uint32_t bWarp = (uint32_t)(wn * 64) * (LDT * 2);

        #pragma unroll
        for (int ks = 0; ks < BK / 16; ++ks) {
            const uint32_t kB = ks * 32;
            uint32_t ah[2][4], al[2][4];
            #pragma unroll
            for (int mi = 0; mi < 2; ++mi) {
                ldsm_x4(ah[mi], Axh + aWarp + (uint32_t)(mi * 16) * (LDT * 2) + kB + aOff);
                ldsm_x4(al[mi], Axl + aWarp + (uint32_t)(mi * 16) * (LDT * 2) + kB + aOff);
            }
            uint32_t b[8][2];
            // ---- kh: dots += xh*kh + xl*kh ----
            #pragma unroll
            for (int nt = 0; nt < 4; ++nt) {
                uint32_t r[4];
                ldsm_x4(r, Bkh + bWarp + (uint32_t)(nt * 16) * (LDT * 2) + kB + bOff);
                b[nt*2][0] = r[0]; b[nt*2][1] = r[1]; b[nt*2+1][0] = r[2]; b[nt*2+1][1] = r[3];
            }
            #pragma unroll
            for (int mi = 0; mi < 2; ++mi)
                #pragma unroll
                for (int ni = 0; ni < 8; ++ni) {
                    mma16816(accD[mi][ni], ah[mi], b[ni]);
                    mma16816(accD[mi][ni], al[mi], b[ni]);
                }
            // ---- mh: comp += xh*mh + xl*mh ----
            #pragma unroll
            for (int nt = 0; nt < 4; ++nt) {
                uint32_t r[4];
                ldsm_x4(r, Bmh + bWarp + (uint32_t)(nt * 16) * (LDT * 2) + kB + bOff);
                b[nt*2][0] = r[0]; b[nt*2][1] = r[1]; b[nt*2+1][0] = r[2]; b[nt*2+1][1] = r[3];
            }
            #pragma unroll
            for (int mi = 0; mi < 2; ++mi)
                #pragma unroll
                for (int ni = 0; ni < 8; ++ni) {
                    mma16816(accC[mi][ni], ah[mi], b[ni]);
                    mma16816(accC[mi][ni], al[mi], b[ni]);
                }
        }
        __syncthreads();
    }

    // ---- epilogue: frags -> SMEM (row-major), then fused scalar pass ----
    float* sD = (float*)smem;            // 128x128 dots  (uses 65536 B)
    float* sC = sD + 128 * 128;          // 128x128 comp  (total 131072 B)
    {
        const int r0 = wm * 32 + (lane >> 2);
        const int c0 = wn * 64 + (lane & 3) * 2;
        #pragma unroll
        for (int mi = 0; mi < 2; ++mi)
            #pragma unroll
            for (int ni = 0; ni < 8; ++ni) {
                const int r = r0 + mi * 16;
                const int c = c0 + ni * 8;
                *(float2*)(sD + r * 128 + c)       = make_float2(accD[mi][ni][0], accD[mi][ni][1]);
                *(float2*)(sD + (r + 8) * 128 + c) = make_float2(accD[mi][ni][2], accD[mi][ni][3]);
                *(float2*)(sC + r * 128 + c)       = make_float2(accC[mi][ni][0], accC[mi][ni][1]);
                *(float2*)(sC + (r + 8) * 128 + c) = make_float2(accC[mi][ni][2], accC[mi][ni][3]);
            }
    }
    __syncthreads();

    const size_t NO = (size_t)NROWS * OUT_F;
    #pragma unroll
    for (int e = 0; e < 16; ++e) {
        const int lin = e * 256 + tid;
        const int row = lin >> 5;
        const int c4  = (lin & 31) * 4;
        const int m   = mBase + row;
        const float xn = g_xnorm[m];
        float4 d = *(float4*)(sD + row * 128 + c4);
        float4 c = *(float4*)(sC + row * 128 + c4);
        float sc[4], mk[4];
        const float* dv = &d.x;
        const float* cv = &c.x;
        #pragma unroll
        for (int j = 0; j < 4; ++j) {
            const int n = nBase + c4 + j;
            const float score = dv[j] / fmaxf(xn * g_knorm[n], 1e-8f);
            const float w = fmaxf(score - gate[n], 0.0f);
            sc[j] = score;
            mk[j] = (cv[j] + bias[n]) * w;
        }
        float4 sc4 = make_float4(sc[0], sc[1], sc[2], sc[3]);
        float4 mk4 = make_float4(mk[0], mk[1], mk[2], mk[3]);
        const size_t idx = (size_t)m * OUT_F + nBase + c4;
        *(float4*)(out + idx)          = mk4;   // output
        *(float4*)(out + NO + idx)     = sc4;   // scores
        *(float4*)(out + 2 * NO + idx) = mk4;   // masked
    }
}

// ---------------------------------------------------------------------------
extern "C" void kernel_launch(void* const* d_in, const int* in_sizes, int n_in,
                              void* d_out, int out_size) {
    const float* x    = (const float*)d_in[0];
    const float* muw  = (const float*)d_in[1];
    const float* sgw  = (const float*)d_in[2];
    const float* gate = (const float*)d_in[3];
    const float* bias = (const float*)d_in[4];
    float* out = (float*)d_out;

    cudaFuncSetAttribute(moie_mma_kernel, cudaFuncAttributeMaxDynamicSharedMemorySize, SMEM_SZ);

    prep_w<<<OUT_F, 256>>>(muw, sgw);
    prep_x<<<NROWS, 256>>>(x);
    dim3 grid(OUT_F / 128, NROWS / 128);
    moie_mma_kernel<<<grid, 256, SMEM_SZ>>>(gate, bias, out);
}

// round 10
// speedup vs baseline: 5.8787x; 1.0714x over previous
#include <cuda_runtime.h>
#include <cuda_fp16.h>
#include <math.h>
#include <stdint.h>

#define IN_F  2048
#define OUT_F 2048
#define NROWS 8192   // 4 * 2048

// ---------------------------------------------------------------------------
// Scratch (__device__ globals; no runtime allocation allowed)
// ---------------------------------------------------------------------------
__device__ __align__(16) __half g_xh[(size_t)NROWS * IN_F];
__device__ __align__(16) __half g_xl[(size_t)NROWS * IN_F];
__device__ __align__(16) __half g_kh[(size_t)OUT_F * IN_F];
__device__ __align__(16) __half g_mh[(size_t)OUT_F * IN_F];
__device__ float g_knorm[OUT_F];
__device__ float g_xnorm[NROWS];

__device__ __forceinline__ float softplus_f(float x) {
    return fmaxf(x, 0.0f) + log1pf(expf(-fabsf(x)));
}

__device__ __forceinline__ void cp16(uint32_t sa, const void* gp) {
    asm volatile("cp.async.cg.shared.global [%0], [%1], 16;"
                 :: "r"(sa), "l"(__cvta_generic_to_global(gp)) : "memory");
}
#define CP_COMMIT() asm volatile("cp.async.commit_group;" ::: "memory")
#define CP_WAIT1()  asm volatile("cp.async.wait_group 1;" ::: "memory")
#define CP_WAIT0()  asm volatile("cp.async.wait_group 0;" ::: "memory")

__device__ __forceinline__ uint32_t smem_u32(const void* p) {
    uint32_t a;
    asm("{ .reg .u64 t; cvta.to.shared.u64 t, %1; cvt.u32.u64 %0, t; }" : "=r"(a) : "l"(p));
    return a;
}

__device__ __forceinline__ void ldsm_x4(uint32_t* r, uint32_t addr) {
    asm volatile("ldmatrix.sync.aligned.m8n8.x4.shared.b16 {%0,%1,%2,%3}, [%4];"
                 : "=r"(r[0]), "=r"(r[1]), "=r"(r[2]), "=r"(r[3]) : "r"(addr));
}

__device__ __forceinline__ void mma16816(float* d, const uint32_t* a, const uint32_t* b) {
    asm volatile("mma.sync.aligned.m16n8k16.row.col.f32.f16.f16.f32 "
                 "{%0,%1,%2,%3}, {%4,%5,%6,%7}, {%8,%9}, {%0,%1,%2,%3};"
                 : "+f"(d[0]), "+f"(d[1]), "+f"(d[2]), "+f"(d[3])
                 : "r"(a[0]), "r"(a[1]), "r"(a[2]), "r"(a[3]), "r"(b[0]), "r"(b[1]));
}

// ---------------------------------------------------------------------------
// Prep 1: keys = muw*softplus(sgw); knorm (exact); store fp16 kh, mh.
// ---------------------------------------------------------------------------
__global__ __launch_bounds__(256) void prep_w(const float* __restrict__ muw,
                                              const float* __restrict__ sgw) {
    const int row = blockIdx.x;
    const int t = threadIdx.x;
    const size_t base = (size_t)row * IN_F + t * 8;
    float k[8], m[8];
    float4 m0 = *(const float4*)(muw + base);
    float4 m1 = *(const float4*)(muw + base + 4);
    float4 s0 = *(const float4*)(sgw + base);
    float4 s1 = *(const float4*)(sgw + base + 4);
    m[0]=m0.x; m[1]=m0.y; m[2]=m0.z; m[3]=m0.w; m[4]=m1.x; m[5]=m1.y; m[6]=m1.z; m[7]=m1.w;
    float s[8] = {s0.x,s0.y,s0.z,s0.w,s1.x,s1.y,s1.z,s1.w};
    float ss = 0.0f;
    #pragma unroll
    for (int j = 0; j < 8; j++) { k[j] = m[j] * softplus_f(s[j]); ss += k[j]*k[j]; }
    #pragma unroll
    for (int j = 0; j < 8; j += 2) {
        *(__half2*)(g_kh + base + j) = __half2(__float2half(k[j]), __float2half(k[j+1]));
        *(__half2*)(g_mh + base + j) = __half2(__float2half(m[j]), __float2half(m[j+1]));
    }
    __shared__ float red[256];
    red[t] = ss;
    __syncthreads();
    for (int st = 128; st > 0; st >>= 1) {
        if (t < st) red[t] += red[t + st];
        __syncthreads();
    }
    if (t == 0) g_knorm[row] = sqrtf(red[0]);
}

// ---------------------------------------------------------------------------
// Prep 2: xnorm; fp16 hi/lo split of x.
// ---------------------------------------------------------------------------
__global__ __launch_bounds__(256) void prep_x(const float* __restrict__ x) {
    const int row = blockIdx.x;
    const int t = threadIdx.x;
    const size_t base = (size_t)row * IN_F + t * 8;
    float4 v0 = *(const float4*)(x + base);
    float4 v1 = *(const float4*)(x + base + 4);
    float v[8] = {v0.x,v0.y,v0.z,v0.w,v1.x,v1.y,v1.z,v1.w};
    float ss = 0.0f;
    #pragma unroll
    for (int j = 0; j < 8; j++) ss += v[j]*v[j];
    #pragma unroll
    for (int j = 0; j < 8; j += 2) {
        __half h0 = __float2half(v[j]),   h1 = __float2half(v[j+1]);
        __half l0 = __float2half(v[j]   - __half2float(h0));
        __half l1 = __float2half(v[j+1] - __half2float(h1));
        *(__half2*)(g_xh + base + j) = __half2(h0, h1);
        *(__half2*)(g_xl + base + j) = __half2(l0, l1);
    }
    __shared__ float red[256];
    red[t] = ss;
    __syncthreads();
    for (int st = 128; st > 0; st >>= 1) {
        if (t < st) red[t] += red[t + st];
        __syncthreads();
    }
    if (t == 0) g_xnorm[row] = sqrtf(red[0]);
}

// ---------------------------------------------------------------------------
// Main kernel: CTA 128x64 (M x N), 8 warps (4 M x 2 N), warp tile 32x32.
// 2 CTAs/SM (regs <=128, smem 64KB). 2-stage cp.async pipeline.
// dots = xh*kh + xl*kh = x*kh ; comp = xh*mh + xl*mh = x*mh. fp32 accum.
// ---------------------------------------------------------------------------
#define BM      128
#define BN      64
#define BK      32
#define LDT     40                        // padded row len (fp16); conflict-free
#define TILE_A  (BM * LDT * 2)            // 10240 bytes (xh / xl)
#define TILE_BT (BN * LDT * 2)            // 5120 bytes  (kh / mh)
#define STAGE_B (2 * TILE_A + 2 * TILE_BT) // 30720 bytes
#define NIT     (IN_F / BK)               // 64
// mainloop: 2 stages = 61440; epilogue: 2 x 128x64 fp32 = 65536. max -> 65536.
#define SMEM_SZ 65536

__global__ __launch_bounds__(256, 2)
void moie_mma_kernel(const float* __restrict__ gate,
                     const float* __restrict__ bias,
                     float* __restrict__ out) {
    extern __shared__ char smem[];
    const uint32_t sbase = smem_u32(smem);
    const int tid  = threadIdx.x;
    const int warp = tid >> 5;
    const int lane = tid & 31;
    const int wm   = warp >> 1;          // 0..3 (M, 32 rows)
    const int wn   = warp & 1;           // 0..1 (N, 32 cols)
    const int mBase = blockIdx.y * BM;
    const int nBase = blockIdx.x * BN;

    float accD[2][4][4];   // dots: 2 m16 x 4 n8
    float accC[2][4][4];   // comp
    #pragma unroll
    for (int i = 0; i < 2; i++)
        #pragma unroll
        for (int j = 0; j < 4; j++)
            #pragma unroll
            for (int q = 0; q < 4; q++) { accD[i][j][q] = 0.0f; accC[i][j][q] = 0.0f; }

    const uint32_t aOff = ((lane & 15) * LDT + (lane >> 4) * 8) * 2;
    const uint32_t bOff = (((lane & 7) | ((lane & 16) >> 1)) * LDT + ((lane >> 3) & 1) * 8) * 2;

    // stage layout: [xh(10240)][xl(10240)][kh(5120)][mh(5120)]
    auto load_stage = [&](int slot, int it) {
        const uint32_t sb = sbase + (uint32_t)slot * STAGE_B;
        const int k0 = it * BK;
        // xh, xl: 128 rows x 4 chunks = 512 cp16 -> 2/thread each
        #pragma unroll
        for (int h = 0; h < 2; ++h) {
            const __half* gp = h ? g_xl : g_xh;
            const uint32_t tb = sb + h * TILE_A;
            #pragma unroll
            for (int t = 0; t < 2; ++t) {
                const int v   = tid + t * 256;      // 0..511
                const int row = v >> 2;
                const int c16 = v & 3;
                cp16(tb + row * (LDT * 2) + c16 * 16,
                     g_xh == gp || g_xl == gp
                         ? gp + (size_t)(mBase + row) * IN_F + k0 + c16 * 8
                         : gp);
            }
        }
        // kh, mh: 64 rows x 4 chunks = 256 cp16 -> 1/thread each
        {
            const int row = tid >> 2;
            const int c16 = tid & 3;
            cp16(sb + 2 * TILE_A + row * (LDT * 2) + c16 * 16,
                 g_kh + (size_t)(nBase + row) * IN_F + k0 + c16 * 8);
            cp16(sb + 2 * TILE_A + TILE_BT + row * (LDT * 2) + c16 * 16,
                 g_mh + (size_t)(nBase + row) * IN_F + k0 + c16 * 8);
        }
    };

    load_stage(0, 0); CP_COMMIT();

    for (int it = 0; it < NIT; ++it) {
        if (it + 1 < NIT) { load_stage((it + 1) & 1, it + 1); CP_COMMIT(); CP_WAIT1(); }
        else              { CP_WAIT0(); }
        __syncthreads();

        const uint32_t st  = sbase + (uint32_t)(it & 1) * STAGE_B;
        const uint32_t Axh = st;
        const uint32_t Axl = st + TILE_A;
        const uint32_t Bkh = st + 2 * TILE_A;
        const uint32_t Bmh = st + 2 * TILE_A + TILE_BT;
        const uint32_t aWarp = (uint32_t)(wm * 32) * (LDT * 2);
        const uint32_t bWarp = (uint32_t)(wn * 32) * (LDT * 2);

        #pragma unroll
        for (int ks = 0; ks < BK / 16; ++ks) {
            const uint32_t kB = ks * 32;
            uint32_t ah[2][4], al[2][4];
            #pragma unroll
            for (int mi = 0; mi < 2; ++mi) {
                ldsm_x4(ah[mi], Axh + aWarp + (uint32_t)(mi * 16) * (LDT * 2) + kB + aOff);
                ldsm_x4(al[mi], Axl + aWarp + (uint32_t)(mi * 16) * (LDT * 2) + kB + aOff);
            }
            uint32_t b[4][2];
            // ---- kh: dots += xh*kh + xl*kh ----
            #pragma unroll
            for (int nt = 0; nt < 2; ++nt) {
                uint32_t r[4];
                ldsm_x4(r, Bkh + bWarp + (uint32_t)(nt * 16) * (LDT * 2) + kB + bOff);
                b[nt*2][0] = r[0]; b[nt*2][1] = r[1]; b[nt*2+1][0] = r[2]; b[nt*2+1][1] = r[3];
            }
            #pragma unroll
            for (int mi = 0; mi < 2; ++mi)
                #pragma unroll
                for (int ni = 0; ni < 4; ++ni) {
                    mma16816(accD[mi][ni], ah[mi], b[ni]);
                    mma16816(accD[mi][ni], al[mi], b[ni]);
                }
            // ---- mh: comp += xh*mh + xl*mh ----
            #pragma unroll
            for (int nt = 0; nt < 2; ++nt) {
                uint32_t r[4];
                ldsm_x4(r, Bmh + bWarp + (uint32_t)(nt * 16) * (LDT * 2) + kB + bOff);
                b[nt*2][0] = r[0]; b[nt*2][1] = r[1]; b[nt*2+1][0] = r[2]; b[nt*2+1][1] = r[3];
            }
            #pragma unroll
            for (int mi = 0; mi < 2; ++mi)
                #pragma unroll
                for (int ni = 0; ni < 4; ++ni) {
                    mma16816(accC[mi][ni], ah[mi], b[ni]);
                    mma16816(accC[mi][ni], al[mi], b[ni]);
                }
        }
        __syncthreads();   // all warps done with slot (it&1) before it is refilled
    }

    // ---- epilogue: frags -> SMEM (row-major 128x64), then fused scalar pass
    float* sD = (float*)smem;            // 128x64 dots  (32768 B)
    float* sC = sD + BM * BN;            // 128x64 comp  (total 65536 B)
    {
        const int r0 = wm * 32 + (lane >> 2);
        const int c0 = wn * 32 + (lane & 3) * 2;
        #pragma unroll
        for (int mi = 0; mi < 2; ++mi)
            #pragma unroll
            for (int ni = 0; ni < 4; ++ni) {
                const int r = r0 + mi * 16;
                const int c = c0 + ni * 8;
                *(float2*)(sD + r * BN + c)       = make_float2(accD[mi][ni][0], accD[mi][ni][1]);
                *(float2*)(sD + (r + 8) * BN + c) = make_float2(accD[mi][ni][2], accD[mi][ni][3]);
                *(float2*)(sC + r * BN + c)       = make_float2(accC[mi][ni][0], accC[mi][ni][1]);
                *(float2*)(sC + (r + 8) * BN + c) = make_float2(accC[mi][ni][2], accC[mi][ni][3]);
            }
    }
    __syncthreads();

    const size_t NO = (size_t)NROWS * OUT_F;
    #pragma unroll
    for (int e = 0; e < 8; ++e) {
        const int lin = e * 256 + tid;       // float4 slot, 0..2047
        const int row = lin >> 4;            // 0..127
        const int c4  = (lin & 15) * 4;      // 0..60
        const int m   = mBase + row;
        const float xn = g_xnorm[m];
        float4 d = *(float4*)(sD + row * BN + c4);
        float4 c = *(float4*)(sC + row * BN + c4);
        float sc[4], mk[4];
        const float* dv = &d.x;
        const float* cv = &c.x;
        #pragma unroll
        for (int j = 0; j < 4; ++j) {
            const int n = nBase + c4 + j;
            const float score = dv[j] / fmaxf(xn * g_knorm[n], 1e-8f);
            const float w = fmaxf(score - gate[n], 0.0f);
            sc[j] = score;
            mk[j] = (cv[j] + bias[n]) * w;
        }
        float4 sc4 = make_float4(sc[0], sc[1], sc[2], sc[3]);
        float4 mk4 = make_float4(mk[0], mk[1], mk[2], mk[3]);
        const size_t idx = (size_t)m * OUT_F + nBase + c4;
        *(float4*)(out + idx)          = mk4;   // output
        *(float4*)(out + NO + idx)     = sc4;   // scores
        *(float4*)(out + 2 * NO + idx) = mk4;   // masked
    }
}

// ---------------------------------------------------------------------------
extern "C" void kernel_launch(void* const* d_in, const int* in_sizes, int n_in,
                              void* d_out, int out_size) {
    const float* x    = (const float*)d_in[0];
    const float* muw  = (const float*)d_in[1];
    const float* sgw  = (const float*)d_in[2];
    const float* gate = (const float*)d_in[3];
    const float* bias = (const float*)d_in[4];
    float* out = (float*)d_out;

    cudaFuncSetAttribute(moie_mma_kernel, cudaFuncAttributeMaxDynamicSharedMemorySize, SMEM_SZ);

    prep_w<<<OUT_F, 256>>>(muw, sgw);
    prep_x<<<NROWS, 256>>>(x);
    dim3 grid(OUT_F / BN, NROWS / BM);
    moie_mma_kernel<<<grid, 256, SMEM_SZ>>>(gate, bias, out);
}

// round 12
// speedup vs baseline: 6.0083x; 1.0220x over previous
#include <cuda_runtime.h>
#include <cuda_fp16.h>
#include <math.h>
#include <stdint.h>

#define IN_F  2048
#define OUT_F 2048
#define NROWS 8192   // 4 * 2048

// ---------------------------------------------------------------------------
// Scratch (__device__ globals; no runtime allocation allowed)
// ---------------------------------------------------------------------------
__device__ __align__(16) __half g_xh[(size_t)NROWS * IN_F];
__device__ __align__(16) __half g_xl[(size_t)NROWS * IN_F];
__device__ __align__(16) __half g_kh[(size_t)OUT_F * IN_F];
__device__ __align__(16) __half g_mh[(size_t)OUT_F * IN_F];
__device__ float g_knorm[OUT_F];
__device__ float g_xnorm[NROWS];

__device__ __forceinline__ float softplus_f(float x) {
    return fmaxf(x, 0.0f) + log1pf(expf(-fabsf(x)));
}

__device__ __forceinline__ void cp16(uint32_t sa, const void* gp) {
    asm volatile("cp.async.cg.shared.global [%0], [%1], 16;"
                 :: "r"(sa), "l"(__cvta_generic_to_global(gp)) : "memory");
}
#define CP_COMMIT() asm volatile("cp.async.commit_group;" ::: "memory")
#define CP_WAIT1()  asm volatile("cp.async.wait_group 1;" ::: "memory")
#define CP_WAIT0()  asm volatile("cp.async.wait_group 0;" ::: "memory")

__device__ __forceinline__ uint32_t smem_u32(const void* p) {
    uint32_t a;
    asm("{ .reg .u64 t; cvta.to.shared.u64 t, %1; cvt.u32.u64 %0, t; }" : "=r"(a) : "l"(p));
    return a;
}

__device__ __forceinline__ void ldsm_x4(uint32_t* r, uint32_t addr) {
    asm volatile("ldmatrix.sync.aligned.m8n8.x4.shared.b16 {%0,%1,%2,%3}, [%4];"
                 : "=r"(r[0]), "=r"(r[1]), "=r"(r[2]), "=r"(r[3]) : "r"(addr));
}

__device__ __forceinline__ void mma16816(float* d, const uint32_t* a, const uint32_t* b) {
    asm volatile("mma.sync.aligned.m16n8k16.row.col.f32.f16.f16.f32 "
                 "{%0,%1,%2,%3}, {%4,%5,%6,%7}, {%8,%9}, {%0,%1,%2,%3};"
                 : "+f"(d[0]), "+f"(d[1]), "+f"(d[2]), "+f"(d[3])
                 : "r"(a[0]), "r"(a[1]), "r"(a[2]), "r"(a[3]), "r"(b[0]), "r"(b[1]));
}

// ---------------------------------------------------------------------------
// Prep 1: keys = muw*softplus(sgw); knorm (exact); store fp16 kh, mh.
// ---------------------------------------------------------------------------
__global__ __launch_bounds__(256) void prep_w(const float* __restrict__ muw,
                                              const float* __restrict__ sgw) {
    const int row = blockIdx.x;
    const int t = threadIdx.x;
    const size_t base = (size_t)row * IN_F + t * 8;
    float k[8], m[8];
    float4 m0 = *(const float4*)(muw + base);
    float4 m1 = *(const float4*)(muw + base + 4);
    float4 s0 = *(const float4*)(sgw + base);
    float4 s1 = *(const float4*)(sgw + base + 4);
    m[0]=m0.x; m[1]=m0.y; m[2]=m0.z; m[3]=m0.w; m[4]=m1.x; m[5]=m1.y; m[6]=m1.z; m[7]=m1.w;
    float s[8] = {s0.x,s0.y,s0.z,s0.w,s1.x,s1.y,s1.z,s1.w};
    float ss = 0.0f;
    #pragma unroll
    for (int j = 0; j < 8; j++) { k[j] = m[j] * softplus_f(s[j]); ss += k[j]*k[j]; }
    #pragma unroll
    for (int j = 0; j < 8; j += 2) {
        *(__half2*)(g_kh + base + j) = __half2(__float2half(k[j]), __float2half(k[j+1]));
        *(__half2*)(g_mh + base + j) = __half2(__float2half(m[j]), __float2half(m[j+1]));
    }
    __shared__ float red[256];
    red[t] = ss;
    __syncthreads();
    for (int st = 128; st > 0; st >>= 1) {
        if (t < st) red[t] += red[t + st];
        __syncthreads();
    }
    if (t == 0) g_knorm[row] = sqrtf(red[0]);
}

// ---------------------------------------------------------------------------
// Prep 2: xnorm; fp16 hi/lo split of x.
// ---------------------------------------------------------------------------
__global__ __launch_bounds__(256) void prep_x(const float* __restrict__ x) {
    const int row = blockIdx.x;
    const int t = threadIdx.x;
    const size_t base = (size_t)row * IN_F + t * 8;
    float4 v0 = *(const float4*)(x + base);
    float4 v1 = *(const float4*)(x + base + 4);
    float v[8] = {v0.x,v0.y,v0.z,v0.w,v1.x,v1.y,v1.z,v1.w};
    float ss = 0.0f;
    #pragma unroll
    for (int j = 0; j < 8; j++) ss += v[j]*v[j];
    #pragma unroll
    for (int j = 0; j < 8; j += 2) {
        __half h0 = __float2half(v[j]),   h1 = __float2half(v[j+1]);
        __half l0 = __float2half(v[j]   - __half2float(h0));
        __half l1 = __float2half(v[j+1] - __half2float(h1));
        *(__half2*)(g_xh + base + j) = __half2(h0, h1);
        *(__half2*)(g_xl + base + j) = __half2(l0, l1);
    }
    __shared__ float red[256];
    red[t] = ss;
    __syncthreads();
    for (int st = 128; st > 0; st >>= 1) {
        if (t < st) red[t] += red[t + st];
        __syncthreads();
    }
    if (t == 0) g_xnorm[row] = sqrtf(red[0]);
}

// ---------------------------------------------------------------------------
// Main kernel: CTA 128x64 (M x N), 8 warps (4 M x 2 N), warp tile 32x32.
// 2 CTAs/SM. 2-stage cp.async pipeline. MMA chains ordered so each
// accumulator's reuse distance is 16 MMAs (no exposed HMMA RAW stalls).
// dots = xh*kh + xl*kh = x*kh ; comp = xh*mh + xl*mh = x*mh. fp32 accum.
// ---------------------------------------------------------------------------
#define BM      128
#define BN      64
#define BK      32
#define LDT     40                        // padded row len (fp16); conflict-free
#define TILE_A  (BM * LDT * 2)            // 10240 bytes (xh / xl)
#define TILE_BT (BN * LDT * 2)            // 5120 bytes  (kh / mh)
#define STAGE_B (2 * TILE_A + 2 * TILE_BT) // 30720 bytes
#define NIT     (IN_F / BK)               // 64
// mainloop: 2 stages = 61440; epilogue: 2 x 128x64 fp32 = 65536. max -> 65536.
#define SMEM_SZ 65536

__global__ __launch_bounds__(256, 2)
void moie_mma_kernel(const float* __restrict__ gate,
                     const float* __restrict__ bias,
                     float* __restrict__ out) {
    extern __shared__ char smem[];
    const uint32_t sbase = smem_u32(smem);
    const int tid  = threadIdx.x;
    const int warp = tid >> 5;
    const int lane = tid & 31;
    const int wm   = warp >> 1;          // 0..3 (M, 32 rows)
    const int wn   = warp & 1;           // 0..1 (N, 32 cols)
    const int mBase = blockIdx.y * BM;
    const int nBase = blockIdx.x * BN;

    float accD[2][4][4];   // dots: 2 m16 x 4 n8
    float accC[2][4][4];   // comp
    #pragma unroll
    for (int i = 0; i < 2; i++)
        #pragma unroll
        for (int j = 0; j < 4; j++)
            #pragma unroll
            for (int q = 0; q < 4; q++) { accD[i][j][q] = 0.0f; accC[i][j][q] = 0.0f; }

    const uint32_t aOff = ((lane & 15) * LDT + (lane >> 4) * 8) * 2;
    const uint32_t bOff = (((lane & 7) | ((lane & 16) >> 1)) * LDT + ((lane >> 3) & 1) * 8) * 2;

    // stage layout: [xh(10240)][xl(10240)][kh(5120)][mh(5120)]
    auto load_stage = [&](int slot, int it) {
        const uint32_t sb = sbase + (uint32_t)slot * STAGE_B;
        const int k0 = it * BK;
        #pragma unroll
        for (int h = 0; h < 2; ++h) {
            const __half* gp = h ? g_xl : g_xh;
            const uint32_t tb = sb + h * TILE_A;
            #pragma unroll
            for (int t = 0; t < 2; ++t) {
                const int v   = tid + t * 256;      // 0..511
                const int row = v >> 2;
                const int c16 = v & 3;
                cp16(tb + row * (LDT * 2) + c16 * 16,
                     gp + (size_t)(mBase + row) * IN_F + k0 + c16 * 8);
            }
        }
        {
            const int row = tid >> 2;
            const int c16 = tid & 3;
            cp16(sb + 2 * TILE_A + row * (LDT * 2) + c16 * 16,
                 g_kh + (size_t)(nBase + row) * IN_F + k0 + c16 * 8);
            cp16(sb + 2 * TILE_A + TILE_BT + row * (LDT * 2) + c16 * 16,
                 g_mh + (size_t)(nBase + row) * IN_F + k0 + c16 * 8);
        }
    };

    load_stage(0, 0); CP_COMMIT();

    for (int it = 0; it < NIT; ++it) {
        if (it + 1 < NIT) { load_stage((it + 1) & 1, it + 1); CP_COMMIT(); CP_WAIT1(); }
        else              { CP_WAIT0(); }
        __syncthreads();

        const uint32_t st  = sbase + (uint32_t)(it & 1) * STAGE_B;
        const uint32_t Axh = st;
        const uint32_t Axl = st + TILE_A;
        const uint32_t Bkh = st + 2 * TILE_A;
        const uint32_t Bmh = st + 2 * TILE_A + TILE_BT;
        const uint32_t aWarp = (uint32_t)(wm * 32) * (LDT * 2);
        const uint32_t bWarp = (uint32_t)(wn * 32) * (LDT * 2);

        #pragma unroll
        for (int ks = 0; ks < BK / 16; ++ks) {
            const uint32_t kB = ks * 32;
            // ---- load ALL operands first ----
            uint32_t ah[2][4], al[2][4];
            #pragma unroll
            for (int mi = 0; mi < 2; ++mi) {
                ldsm_x4(ah[mi], Axh + aWarp + (uint32_t)(mi * 16) * (LDT * 2) + kB + aOff);
                ldsm_x4(al[mi], Axl + aWarp + (uint32_t)(mi * 16) * (LDT * 2) + kB + aOff);
            }
            uint32_t bk[4][2], bm[4][2];
            #pragma unroll
            for (int nt = 0; nt < 2; ++nt) {
                uint32_t r[4];
                ldsm_x4(r, Bkh + bWarp + (uint32_t)(nt * 16) * (LDT * 2) + kB + bOff);
                bk[nt*2][0] = r[0]; bk[nt*2][1] = r[1]; bk[nt*2+1][0] = r[2]; bk[nt*2+1][1] = r[3];
                ldsm_x4(r, Bmh + bWarp + (uint32_t)(nt * 16) * (LDT * 2) + kB + bOff);
                bm[nt*2][0] = r[0]; bm[nt*2][1] = r[1]; bm[nt*2+1][0] = r[2]; bm[nt*2+1][1] = r[3];
            }
            // ---- 32 MMAs in 4 groups of 8 independent accumulators ----
            // group 1: accD <- ah*bk  (8 distinct accs)
            #pragma unroll
            for (int mi = 0; mi < 2; ++mi)
                #pragma unroll
                for (int ni = 0; ni < 4; ++ni)
                    mma16816(accD[mi][ni], ah[mi], bk[ni]);
            // group 2: accC <- ah*bm
            #pragma unroll
            for (int mi = 0; mi < 2; ++mi)
                #pragma unroll
                for (int ni = 0; ni < 4; ++ni)
                    mma16816(accC[mi][ni], ah[mi], bm[ni]);
            // group 3: accD <- al*bk   (reuse distance 16 from group 1)
            #pragma unroll
            for (int mi = 0; mi < 2; ++mi)
                #pragma unroll
                for (int ni = 0; ni < 4; ++ni)
                    mma16816(accD[mi][ni], al[mi], bk[ni]);
            // group 4: accC <- al*bm
            #pragma unroll
            for (int mi = 0; mi < 2; ++mi)
                #pragma unroll
                for (int ni = 0; ni < 4; ++ni)
                    mma16816(accC[mi][ni], al[mi], bm[ni]);
        }
        __syncthreads();   // all warps done with slot (it&1) before refill
    }

    // ---- epilogue: frags -> SMEM (row-major 128x64), then fused scalar pass
    float* sD = (float*)smem;            // 128x64 dots  (32768 B)
    float* sC = sD + BM * BN;            // 128x64 comp  (total 65536 B)
    {
        const int r0 = wm * 32 + (lane >> 2);
        const int c0 = wn * 32 + (lane & 3) * 2;
        #pragma unroll
        for (int mi = 0; mi < 2; ++mi)
            #pragma unroll
            for (int ni = 0; ni < 4; ++ni) {
                const int r = r0 + mi * 16;
                const int c = c0 + ni * 8;
                *(float2*)(sD + r * BN + c)       = make_float2(accD[mi][ni][0], accD[mi][ni][1]);
                *(float2*)(sD + (r + 8) * BN + c) = make_float2(accD[mi][ni][2], accD[mi][ni][3]);
                *(float2*)(sC + r * BN + c)       = make_float2(accC[mi][ni][0], accC[mi][ni][1]);
                *(float2*)(sC + (r + 8) * BN + c) = make_float2(accC[mi][ni][2], accC[mi][ni][3]);
            }
    }
    __syncthreads();

    const size_t NO = (size_t)NROWS * OUT_F;
    #pragma unroll
    for (int e = 0; e < 8; ++e) {
        const int lin = e * 256 + tid;       // float4 slot, 0..2047
        const int row = lin >> 4;            // 0..127
        const int c4  = (lin & 15) * 4;      // 0..60
        const int m   = mBase + row;
        const float xn = g_xnorm[m];
        float4 d = *(float4*)(sD + row * BN + c4);
        float4 c = *(float4*)(sC + row * BN + c4);
        float sc[4], mk[4];
        const float* dv = &d.x;
        const float* cv = &c.x;
        #pragma unroll
        for (int j = 0; j < 4; ++j) {
            const int n = nBase + c4 + j;
            const float score = dv[j] / fmaxf(xn * g_knorm[n], 1e-8f);
            const float w = fmaxf(score - gate[n], 0.0f);
            sc[j] = score;
            mk[j] = (cv[j] + bias[n]) * w;
        }
        float4 sc4 = make_float4(sc[0], sc[1], sc[2], sc[3]);
        float4 mk4 = make_float4(mk[0], mk[1], mk[2], mk[3]);
        const size_t idx = (size_t)m * OUT_F + nBase + c4;
        *(float4*)(out + idx)          = mk4;   // output
        *(float4*)(out + NO + idx)     = sc4;   // scores
        *(float4*)(out + 2 * NO + idx) = mk4;   // masked
    }
}

// ---------------------------------------------------------------------------
extern "C" void kernel_launch(void* const* d_in, const int* in_sizes, int n_in,
                              void* d_out, int out_size) {
    const float* x    = (const float*)d_in[0];
    const float* muw  = (const float*)d_in[1];
    const float* sgw  = (const float*)d_in[2];
    const float* gate = (const float*)d_in[3];
    const float* bias = (const float*)d_in[4];
    float* out = (float*)d_out;

    cudaFuncSetAttribute(moie_mma_kernel, cudaFuncAttributeMaxDynamicSharedMemorySize, SMEM_SZ);

    prep_w<<<OUT_F, 256>>>(muw, sgw);
    prep_x<<<NROWS, 256>>>(x);
    dim3 grid(OUT_F / BN, NROWS / BM);
    moie_mma_kernel<<<grid, 256, SMEM_SZ>>>(gate, bias, out);
}